// round 10
// baseline (speedup 1.0000x reference)
#include <cuda_runtime.h>
#include <cstdint>
#include <cstddef>

#define BB 8
#define SS 4096
#define DD 256
#define GG 512      // big chunk
#define NG 8        // big chunks per batch
#define NBG 64      // total big chunks
#define CI 32       // inner chunk
#define NIC 16      // inner chunks per big chunk

// Scratch: per-big-chunk state^T [bg][j][d]; LB converts in place to the
// state ENTERING each big chunk (16.8 MB).
__device__ float g_S[(size_t)NBG * DD * DD];
__device__ float g_Lg[NBG * GG];
__device__ float g_Gamma[NBG];

// ---------------------------------------------------------------------------
// Helpers
// ---------------------------------------------------------------------------
__device__ __forceinline__ uint32_t smem_u32(const void* p) {
    uint32_t a;
    asm("{ .reg .u64 t; cvta.to.shared.u64 t, %1; cvt.u32.u64 %0, t; }"
        : "=r"(a) : "l"(p));
    return a;
}

__device__ __forceinline__ float to_tf32(float f) {
    uint32_t r;
    asm("cvt.rna.tf32.f32 %0, %1;" : "=r"(r) : "f"(f));
    return __uint_as_float(r);
}

__device__ __forceinline__ void mma_tf32(float c[4], const uint32_t a[4],
                                         const uint32_t b[2]) {
    asm volatile(
        "mma.sync.aligned.m16n8k8.row.col.f32.tf32.tf32.f32 "
        "{%0,%1,%2,%3}, {%4,%5,%6,%7}, {%8,%9}, {%0,%1,%2,%3};"
        : "+f"(c[0]), "+f"(c[1]), "+f"(c[2]), "+f"(c[3])
        : "r"(a[0]), "r"(a[1]), "r"(a[2]), "r"(a[3]), "r"(b[0]), "r"(b[1]));
}

__device__ __forceinline__ void ldmx4(uint32_t r[4], uint32_t a) {
    asm volatile("ldmatrix.sync.aligned.m8n8.x4.shared.b16 {%0,%1,%2,%3}, [%4];"
                 : "=r"(r[0]), "=r"(r[1]), "=r"(r[2]), "=r"(r[3]) : "r"(a));
}
__device__ __forceinline__ void ldmx2(uint32_t r[2], uint32_t a) {
    asm volatile("ldmatrix.sync.aligned.m8n8.x2.shared.b16 {%0,%1}, [%2];"
                 : "=r"(r[0]), "=r"(r[1]) : "r"(a));
}

__device__ __forceinline__ void cp16(uint32_t dst, const void* src) {
    asm volatile("cp.async.cg.shared.global [%0], [%1], 16;"
                 :: "r"(dst), "l"(src));
}
#define CP_COMMIT() asm volatile("cp.async.commit_group;" ::: "memory")
#define CP_WAIT0()  asm volatile("cp.async.wait_group 0;" ::: "memory")

// fp32 smem strides (words), ≡ 4 (mod 32): conflict-free b16-trick ldmatrix
#define SD4 260   // 256-wide rows
#define SV4 132   // 128-wide rows
#define SA4 36    // 32-wide rows
#define SKT 36    // Kt rows (32 taus + pad)

// RZ-truncation bias compensation (HMMA truncates fp32 operands to tf32).
#define CF1X 1.000338f
#define CF2X 1.000677f
#define CF3X 1.001015f

// ---------------------------------------------------------------------------
// LA: big-chunk state contribution T^T[j][d] per (bg, j-half). 512 threads.
// (verbatim from R9 — verified)
// ---------------------------------------------------------------------------
#define A_LGG 0
#define A_WV  2048
#define A_K0  4096
#define A_K1  (A_K0 + 64 * SD4 * 4)
#define A_V0  (A_K1 + 64 * SD4 * 4)
#define A_V1  (A_V0 + 64 * SV4 * 4)
#define A_SMEM (A_V1 + 64 * SV4 * 4)   // 204800

__global__ __launch_bounds__(512, 1) void dr_state(
    const float* __restrict__ K, const float* __restrict__ V,
    const float* __restrict__ beta)
{
    extern __shared__ char sm[];
    float* Lgg = (float*)(sm + A_LGG);
    float* wv  = (float*)(sm + A_WV);
    const uint32_t sb = smem_u32(sm);
    const int bg = blockIdx.x, qj = blockIdx.y;
    const int b = bg >> 3, g2 = bg & 7;
    const int tid = threadIdx.x, wid = tid >> 5, lane = tid & 31;
    const int q = lane & 3, g = lane >> 2;

    const size_t tok0 = (size_t)b * SS + (size_t)g2 * GG;
    const float* Kg = K + tok0 * DD;
    const float* Vg = V + tok0 * DD + qj * 128;

    {
        uint32_t kd = sb + A_K0, vd = sb + A_V0;
        #pragma unroll
        for (int it = 0; it < 8; it++) {
            int idx = it * 512 + tid, row = idx >> 6, c4 = (idx & 63) << 2;
            cp16(kd + (uint32_t)(row * SD4 + c4) * 4, Kg + (size_t)row * DD + c4);
        }
        #pragma unroll
        for (int it = 0; it < 4; it++) {
            int idx = it * 512 + tid, row = idx >> 5, c4 = (idx & 31) << 2;
            cp16(vd + (uint32_t)(row * SV4 + c4) * 4, Vg + (size_t)row * DD + c4);
        }
        CP_COMMIT();
    }

    Lgg[tid] = __logf(fmaxf(beta[tok0 + tid], 1e-30f));
    __syncthreads();
    if (wid == 0) {
        int b0 = lane * 16;
        float s = 0.f;
        #pragma unroll
        for (int u = 0; u < 16; u++) { s += Lgg[b0 + u]; Lgg[b0 + u] = s; }
        float t = s;
        #pragma unroll
        for (int d = 1; d < 32; d <<= 1) {
            float o = __shfl_up_sync(0xFFFFFFFFu, t, d);
            if (lane >= d) t += o;
        }
        float excl = t - s;
        #pragma unroll
        for (int u = 0; u < 16; u++) Lgg[b0 + u] += excl;
    }
    __syncthreads();
    const float lend = Lgg[GG - 1];
    wv[tid] = __expf(lend - Lgg[tid]) * CF1X;
    if (qj == 0) {
        g_Lg[bg * GG + tid] = Lgg[tid];
        if (tid == 0) g_Gamma[bg] = __expf(lend);
    }

    const int jm0 = (wid >> 2) * 32;
    const int i0w = (wid & 3) * 64;

    float acc[2][8][4];
    #pragma unroll
    for (int mt = 0; mt < 2; mt++)
        #pragma unroll
        for (int nt = 0; nt < 8; nt++)
            #pragma unroll
            for (int u = 0; u < 4; u++) acc[mt][nt][u] = 0.f;

    for (int p = 0; p < 8; p++) {
        CP_WAIT0();
        __syncthreads();
        if (p < 7) {
            uint32_t kd = sb + (((p + 1) & 1) ? A_K1 : A_K0);
            uint32_t vd = sb + (((p + 1) & 1) ? A_V1 : A_V0);
            const float* Kn = Kg + (size_t)(p + 1) * 64 * DD;
            const float* Vn = Vg + (size_t)(p + 1) * 64 * DD;
            #pragma unroll
            for (int it = 0; it < 8; it++) {
                int idx = it * 512 + tid, row = idx >> 6, c4 = (idx & 63) << 2;
                cp16(kd + (uint32_t)(row * SD4 + c4) * 4, Kn + (size_t)row * DD + c4);
            }
            #pragma unroll
            for (int it = 0; it < 4; it++) {
                int idx = it * 512 + tid, row = idx >> 5, c4 = (idx & 31) << 2;
                cp16(vd + (uint32_t)(row * SV4 + c4) * 4, Vn + (size_t)row * DD + c4);
            }
            CP_COMMIT();
        }
        const float* Kp = (const float*)(sm + ((p & 1) ? A_K1 : A_K0));
        const float* Vp = (const float*)(sm + ((p & 1) ? A_V1 : A_V0));
        const float* wp = wv + p * 64;

        #pragma unroll
        for (int k0 = 0; k0 < 64; k0 += 8) {
            const int r0 = (k0 + q) * SV4, r4 = (k0 + 4 + q) * SV4;
            const int s0 = (k0 + q) * SD4, s4 = (k0 + 4 + q) * SD4;
            const float w0 = wp[k0 + q], w1 = wp[k0 + 4 + q];
            uint32_t af[2][4], bf[8][2];
            #pragma unroll
            for (int mt = 0; mt < 2; mt++) {
                int jb = jm0 + mt * 16 + g;
                af[mt][0] = __float_as_uint(to_tf32(Vp[r0 + jb] * w0));
                af[mt][1] = __float_as_uint(to_tf32(Vp[r0 + jb + 8] * w0));
                af[mt][2] = __float_as_uint(to_tf32(Vp[r4 + jb] * w1));
                af[mt][3] = __float_as_uint(to_tf32(Vp[r4 + jb + 8] * w1));
            }
            #pragma unroll
            for (int nt = 0; nt < 8; nt++) {
                int db = i0w + nt * 8 + g;
                bf[nt][0] = __float_as_uint(Kp[s0 + db]);
                bf[nt][1] = __float_as_uint(Kp[s4 + db]);
            }
            #pragma unroll
            for (int mt = 0; mt < 2; mt++)
                #pragma unroll
                for (int nt = 0; nt < 8; nt++)
                    mma_tf32(acc[mt][nt], af[mt], bf[nt]);
        }
    }

    float* Sdst = g_S + (size_t)bg * 65536 + (size_t)(qj * 128) * 256;
    #pragma unroll
    for (int mt = 0; mt < 2; mt++)
        #pragma unroll
        for (int nt = 0; nt < 8; nt++) {
            int j = jm0 + mt * 16 + g;
            int d = i0w + nt * 8 + 2 * q;
            float2 v0 = { acc[mt][nt][0], acc[mt][nt][1] };
            float2 v1 = { acc[mt][nt][2], acc[mt][nt][3] };
            *(float2*)(Sdst + (size_t)j * 256 + d) = v0;
            *(float2*)(Sdst + (size_t)(j + 8) * 256 + d) = v1;
        }
}

// ---------------------------------------------------------------------------
// LB: 8-step scan over big-chunk states (in place). (verbatim R9)
// ---------------------------------------------------------------------------
__global__ __launch_bounds__(256) void dr_scan()
{
    const int b = blockIdx.y;
    const size_t e4 = ((size_t)blockIdx.x * 256 + threadIdx.x) * 4;
    float4 h = { 0.f, 0.f, 0.f, 0.f };
    #pragma unroll
    for (int g2 = 0; g2 < NG; g2++) {
        const int bg = b * NG + g2;
        const size_t off = (size_t)bg * 65536 + e4;
        const float gc = g_Gamma[bg];
        float4 s = *(const float4*)(g_S + off);
        *(float4*)(g_S + off) = h;
        h.x = gc * h.x + s.x; h.y = gc * h.y + s.y;
        h.z = gc * h.z + s.z; h.w = gc * h.w + s.w;
    }
}

// ---------------------------------------------------------------------------
// LC: fused per-(bg, jh). State stored TRANSPOSED: each warp owns 8
// j-columns x all 256 d as update-MMA accumulators C[m=d16][n=j8]
// (16 tiles x 4 regs). Q@H B-frags come straight from state regs via 4
// shuffles/k-tile; state-update A-frags via ldmx4 on a per-chunk K
// transpose Kt[d][tau]; O stores coalesced.
// ---------------------------------------------------------------------------
#define C_LGG 0
#define C_WV  2048
#define C_SG  2176
#define C_Q0  2304
#define C_Q1  (C_Q0 + 32 * SD4 * 4)     // 35584
#define C_KST (C_Q1 + 32 * SD4 * 4)     // 68864 (K staging, natural [tau][d])
#define C_KT  (C_KST + 32 * SD4 * 4)    // 102144 (Kt[d 256][tau 32])
#define C_V0  (C_KT + 256 * SKT * 4)    // 139008
#define C_V1  (C_V0 + 32 * SV4 * 4)     // 155904
#define C_AS  (C_V1 + 32 * SV4 * 4)     // 172800
#define C_SMEM (C_AS + 32 * SA4 * 4)    // 177408

__global__ __launch_bounds__(512, 1) void dr_out(
    const float* __restrict__ Q, const float* __restrict__ K,
    const float* __restrict__ V, float* __restrict__ O)
{
    extern __shared__ char sm[];
    float* Lgg = (float*)(sm + C_LGG);
    float* wv  = (float*)(sm + C_WV);
    float* sg  = (float*)(sm + C_SG);
    float* Kst = (float*)(sm + C_KST);
    float* Ktf = (float*)(sm + C_KT);
    float* Asf = (float*)(sm + C_AS);
    const uint32_t sb = smem_u32(sm);

    const int bg = blockIdx.x, jh = blockIdx.y;
    const int b = bg >> 3, g2 = bg & 7;
    const int tid = threadIdx.x, wid = tid >> 5, lane = tid & 31;
    const int q = lane & 3, g = lane >> 2;
    const int rA = lane & 15, cA = (lane >> 4) * 4;

    const size_t tok0 = (size_t)b * SS + (size_t)g2 * GG;
    const float* Qg = Q + tok0 * DD;
    const float* Kg = K + tok0 * DD;
    const float* Vg = V + tok0 * DD + jh * 128;

    Lgg[tid] = g_Lg[bg * GG + tid];

    // --- stage incoming state [j][d] coalesced, gather transposed regs ---
    const int jw = wid * 8;                 // this warp's 8 j-columns
    float st[16][4];
    {
        float* stg = (float*)(sm + C_Q0);   // 128 x SD4 staging (133KB fits)
        const float* Sg = g_S + (size_t)bg * 65536 + (size_t)(jh * 128) * 256;
        #pragma unroll
        for (int it = 0; it < 16; it++) {
            int idx = it * 512 + tid;       // 0..8191 float4s
            int row = idx >> 6, c4 = (idx & 63) << 2;
            float4 hv = *(const float4*)(Sg + (size_t)row * 256 + c4);
            stg[row * SD4 + c4 + 0] = hv.x;
            stg[row * SD4 + c4 + 1] = hv.y;
            stg[row * SD4 + c4 + 2] = hv.z;
            stg[row * SD4 + c4 + 3] = hv.w;
        }
        __syncthreads();
        #pragma unroll
        for (int nt = 0; nt < 16; nt++) {
            int d0 = nt * 16;
            st[nt][0] = stg[(jw + 2 * q) * SD4 + d0 + g];
            st[nt][1] = stg[(jw + 2 * q + 1) * SD4 + d0 + g];
            st[nt][2] = stg[(jw + 2 * q) * SD4 + d0 + 8 + g];
            st[nt][3] = stg[(jw + 2 * q + 1) * SD4 + d0 + 8 + g];
        }
        __syncthreads();                    // staging region free
    }

    // --- issue chunk 0 loads ---
    {
        uint32_t qd = sb + C_Q0, kd = sb + C_KST, vd = sb + C_V0;
        #pragma unroll
        for (int it = 0; it < 4; it++) {
            int idx = it * 512 + tid, row = idx >> 6, c4 = (idx & 63) << 2;
            cp16(qd + (uint32_t)(row * SD4 + c4) * 4, Qg + (size_t)row * DD + c4);
            cp16(kd + (uint32_t)(row * SD4 + c4) * 4, Kg + (size_t)row * DD + c4);
        }
        #pragma unroll
        for (int it = 0; it < 2; it++) {
            int idx = it * 512 + tid, row = idx >> 5, c4 = (idx & 31) << 2;
            cp16(vd + (uint32_t)(row * SV4 + c4) * 4, Vg + (size_t)row * DD + c4);
        }
        CP_COMMIT();
    }

    const int src0 = q * 4 + (g >> 1);      // Q@H B-frag shuffle sources
    const int src1 = src0 + 16;
    const uint32_t ktb = sb + C_KT, asb = sb + C_AS;

    for (int ic = 0; ic < NIC; ic++) {
        const int icb = ic * CI;
        CP_WAIT0();
        __syncthreads();                    // B0: prior Kt/As readers done

        // transpose Kstage[tau][d] -> Kt[d][tau]
        #pragma unroll
        for (int it = 0; it < 4; it++) {
            int idx = it * 512 + tid;       // 0..2047 float4s
            int tau = idx >> 6, d4 = (idx & 63) << 2;
            float4 kv = *(const float4*)(Kst + tau * SD4 + d4);
            Ktf[(d4 + 0) * SKT + tau] = kv.x;
            Ktf[(d4 + 1) * SKT + tau] = kv.y;
            Ktf[(d4 + 2) * SKT + tau] = kv.z;
            Ktf[(d4 + 3) * SKT + tau] = kv.w;
        }
        const float baseL = ic ? Lgg[icb - 1] : 0.f;
        const float lendI = Lgg[icb + CI - 1];
        if (tid < CI) {
            float lt = Lgg[icb + tid];
            wv[tid] = __expf(lendI - lt) * CF1X;
            sg[tid] = __expf(lt - baseL) * CF2X;
        }
        __syncthreads();                    // B1: Kt + wv/sg ready, Kst free

        if (ic < NIC - 1) {
            uint32_t qd = sb + (((ic + 1) & 1) ? C_Q1 : C_Q0);
            uint32_t vd = sb + (((ic + 1) & 1) ? C_V1 : C_V0);
            uint32_t kd = sb + C_KST;
            const float* Qn = Qg + (size_t)(icb + CI) * DD;
            const float* Kn = Kg + (size_t)(icb + CI) * DD;
            const float* Vn = Vg + (size_t)(icb + CI) * DD;
            #pragma unroll
            for (int it = 0; it < 4; it++) {
                int idx = it * 512 + tid, row = idx >> 6, c4 = (idx & 63) << 2;
                cp16(qd + (uint32_t)(row * SD4 + c4) * 4, Qn + (size_t)row * DD + c4);
                cp16(kd + (uint32_t)(row * SD4 + c4) * 4, Kn + (size_t)row * DD + c4);
            }
            #pragma unroll
            for (int it = 0; it < 2; it++) {
                int idx = it * 512 + tid, row = idx >> 5, c4 = (idx & 31) << 2;
                cp16(vd + (uint32_t)(row * SV4 + c4) * 4, Vn + (size_t)row * DD + c4);
            }
            CP_COMMIT();
        }

        const uint32_t qbc = sb + ((ic & 1) ? C_Q1 : C_Q0);
        const float* Vc = (const float*)(sm + ((ic & 1) ? C_V1 : C_V0));

        // ---- Phase A ----
        // all warps: O-acc = Q @ H (B-frags from state regs via shuffles)
        float accO[2][4];
        #pragma unroll
        for (int mt = 0; mt < 2; mt++)
            #pragma unroll
            for (int u = 0; u < 4; u++) accO[mt][u] = 0.f;

        #pragma unroll
        for (int kt = 0; kt < 32; kt++) {
            const int nt = kt >> 1;
            const int lo = (kt & 1) ? 2 : 0;
            float sa0 = __shfl_sync(0xFFFFFFFFu, st[nt][lo],     src0);
            float sa1 = __shfl_sync(0xFFFFFFFFu, st[nt][lo + 1], src0);
            float sb0 = __shfl_sync(0xFFFFFFFFu, st[nt][lo],     src1);
            float sb1 = __shfl_sync(0xFFFFFFFFu, st[nt][lo + 1], src1);
            uint32_t bf[2] = { __float_as_uint((g & 1) ? sa1 : sa0),
                               __float_as_uint((g & 1) ? sb1 : sb0) };
            #pragma unroll
            for (int mt = 0; mt < 2; mt++) {
                uint32_t af[4];
                ldmx4(af, qbc + (uint32_t)((mt * 16 + rA) * SD4 + kt * 8 + cA) * 4);
                mma_tf32(accO[mt], af, bf);
            }
        }

        if (!(wid & 1)) {
            // even warps: QK^T -> masked decayed A
            int e = wid >> 1;
            int i0q = (e >> 2) * 16, t0q = (e & 3) * 8;
            float a1[4] = { 0.f, 0.f, 0.f, 0.f };
            #pragma unroll
            for (int k0 = 0; k0 < 256; k0 += 8) {
                uint32_t af[4];
                ldmx4(af, qbc + (uint32_t)((i0q + rA) * SD4 + k0 + cA) * 4);
                uint32_t bf[2] = {
                    __float_as_uint(Ktf[(k0 + q) * SKT + t0q + g]),
                    __float_as_uint(Ktf[(k0 + 4 + q) * SKT + t0q + g]) };
                mma_tf32(a1, af, bf);
            }
            int ia = i0q + g, ib2 = ia + 8, t = t0q + 2 * q;
            float lia = Lgg[icb + ia], lib = Lgg[icb + ib2];
            float lt0 = Lgg[icb + t], lt1 = Lgg[icb + t + 1];
            float f00 = (t     <= ia)  ? __expf(lia - lt0) * CF3X : 0.f;
            float f01 = (t + 1 <= ia)  ? __expf(lia - lt1) * CF3X : 0.f;
            float f10 = (t     <= ib2) ? __expf(lib - lt0) * CF3X : 0.f;
            float f11 = (t + 1 <= ib2) ? __expf(lib - lt1) * CF3X : 0.f;
            *(float2*)(Asf + ia * SA4 + t) =
                make_float2(to_tf32(a1[0] * f00), to_tf32(a1[1] * f01));
            *(float2*)(Asf + ib2 * SA4 + t) =
                make_float2(to_tf32(a1[2] * f10), to_tf32(a1[3] * f11));
        } else {
            // odd warps: state update  st = gamma*st + K^T (wV)
            const float gamma = __expf(lendI - baseL);
            #pragma unroll
            for (int nt = 0; nt < 16; nt++) {
                st[nt][0] *= gamma; st[nt][1] *= gamma;
                st[nt][2] *= gamma; st[nt][3] *= gamma;
            }
            #pragma unroll
            for (int t0 = 0; t0 < CI; t0 += 8) {
                const float w0 = wv[t0 + q], w1 = wv[t0 + 4 + q];
                uint32_t bf[2] = {
                    __float_as_uint(to_tf32(Vc[(t0 + q) * SV4 + jw + g] * w0)),
                    __float_as_uint(to_tf32(Vc[(t0 + 4 + q) * SV4 + jw + g] * w1)) };
                #pragma unroll
                for (int nt = 0; nt < 16; nt++) {
                    uint32_t af[4];
                    ldmx4(af, ktb + (uint32_t)((nt * 16 + rA) * SKT + t0 + cA) * 4);
                    mma_tf32(st[nt], af, bf);
                }
            }
        }
        __syncthreads();                    // B2: As visible

        // ---- Phase B ----
        // all warps: scale by g, add A@V, store O
        #pragma unroll
        for (int mt = 0; mt < 2; mt++) {
            float sa = sg[mt * 16 + g], sb2 = sg[mt * 16 + 8 + g];
            accO[mt][0] *= sa;  accO[mt][1] *= sa;
            accO[mt][2] *= sb2; accO[mt][3] *= sb2;
        }
        #pragma unroll
        for (int t0 = 0; t0 < CI; t0 += 8) {
            uint32_t bf[2] = {
                __float_as_uint(Vc[(t0 + q) * SV4 + jw + g]),
                __float_as_uint(Vc[(t0 + 4 + q) * SV4 + jw + g]) };
            #pragma unroll
            for (int mt = 0; mt < 2; mt++) {
                uint32_t af[4];
                ldmx4(af, asb + (uint32_t)((mt * 16 + rA) * SA4 + t0 + cA) * 4);
                mma_tf32(accO[mt], af, bf);
            }
        }
        #pragma unroll
        for (int mt = 0; mt < 2; mt++) {
            size_t r0 = (tok0 + icb + mt * 16 + g) * DD + jh * 128 + jw;
            size_t r1 = (tok0 + icb + mt * 16 + 8 + g) * DD + jh * 128 + jw;
            *(float2*)(O + r0 + 2 * q) = make_float2(accO[mt][0], accO[mt][1]);
            *(float2*)(O + r1 + 2 * q) = make_float2(accO[mt][2], accO[mt][3]);
        }

        if (!(wid & 1)) {
            // even warps: state update
            const float gamma = __expf(lendI - baseL);
            #pragma unroll
            for (int nt = 0; nt < 16; nt++) {
                st[nt][0] *= gamma; st[nt][1] *= gamma;
                st[nt][2] *= gamma; st[nt][3] *= gamma;
            }
            #pragma unroll
            for (int t0 = 0; t0 < CI; t0 += 8) {
                const float w0 = wv[t0 + q], w1 = wv[t0 + 4 + q];
                uint32_t bf[2] = {
                    __float_as_uint(to_tf32(Vc[(t0 + q) * SV4 + jw + g] * w0)),
                    __float_as_uint(to_tf32(Vc[(t0 + 4 + q) * SV4 + jw + g] * w1)) };
                #pragma unroll
                for (int nt = 0; nt < 16; nt++) {
                    uint32_t af[4];
                    ldmx4(af, ktb + (uint32_t)((nt * 16 + rA) * SKT + t0 + cA) * 4);
                    mma_tf32(st[nt], af, bf);
                }
            }
        }
    }
}

// ---------------------------------------------------------------------------
extern "C" void kernel_launch(void* const* d_in, const int* in_sizes, int n_in,
                              void* d_out, int out_size)
{
    const float* q    = (const float*)d_in[0];
    const float* k    = (const float*)d_in[1];
    const float* v    = (const float*)d_in[2];
    const float* beta = (const float*)d_in[3];
    float* out = (float*)d_out;
    (void)in_sizes; (void)n_in; (void)out_size;

    cudaFuncSetAttribute(dr_state, cudaFuncAttributeMaxDynamicSharedMemorySize, A_SMEM);
    cudaFuncSetAttribute(dr_out,   cudaFuncAttributeMaxDynamicSharedMemorySize, C_SMEM);

    dr_state<<<dim3(NBG, 2), 512, A_SMEM>>>(k, v, beta);
    dr_scan<<<dim3(64, BB), 256>>>();
    dr_out<<<dim3(NBG, 2), 512, C_SMEM>>>(q, k, v, out);
}

// round 11
// speedup vs baseline: 1.1976x; 1.1976x over previous
#include <cuda_runtime.h>
#include <cstdint>
#include <cstddef>

#define BB 8
#define SS 4096
#define DD 256
#define GG 512      // big chunk
#define NG 8        // big chunks per batch
#define NBG 64      // total big chunks
#define CI 32       // inner chunk
#define NIC 16      // inner chunks per big chunk

// Scratch: per-big-chunk state^T [bg][j][d]; LB converts in place to the
// state ENTERING each big chunk (16.8 MB).
__device__ float g_S[(size_t)NBG * DD * DD];
__device__ float g_Lg[NBG * GG];
__device__ float g_Gamma[NBG];

// ---------------------------------------------------------------------------
// Helpers
// ---------------------------------------------------------------------------
__device__ __forceinline__ uint32_t smem_u32(const void* p) {
    uint32_t a;
    asm("{ .reg .u64 t; cvta.to.shared.u64 t, %1; cvt.u32.u64 %0, t; }"
        : "=r"(a) : "l"(p));
    return a;
}

__device__ __forceinline__ float to_tf32(float f) {
    uint32_t r;
    asm("cvt.rna.tf32.f32 %0, %1;" : "=r"(r) : "f"(f));
    return __uint_as_float(r);
}

__device__ __forceinline__ void mma_tf32(float c[4], const uint32_t a[4],
                                         const uint32_t b[2]) {
    asm volatile(
        "mma.sync.aligned.m16n8k8.row.col.f32.tf32.tf32.f32 "
        "{%0,%1,%2,%3}, {%4,%5,%6,%7}, {%8,%9}, {%0,%1,%2,%3};"
        : "+f"(c[0]), "+f"(c[1]), "+f"(c[2]), "+f"(c[3])
        : "r"(a[0]), "r"(a[1]), "r"(a[2]), "r"(a[3]), "r"(b[0]), "r"(b[1]));
}

__device__ __forceinline__ void ldmx4(uint32_t r[4], uint32_t a) {
    asm volatile("ldmatrix.sync.aligned.m8n8.x4.shared.b16 {%0,%1,%2,%3}, [%4];"
                 : "=r"(r[0]), "=r"(r[1]), "=r"(r[2]), "=r"(r[3]) : "r"(a));
}
__device__ __forceinline__ void ldmx2(uint32_t r[2], uint32_t a) {
    asm volatile("ldmatrix.sync.aligned.m8n8.x2.shared.b16 {%0,%1}, [%2];"
                 : "=r"(r[0]), "=r"(r[1]) : "r"(a));
}

__device__ __forceinline__ void cp16(uint32_t dst, const void* src) {
    asm volatile("cp.async.cg.shared.global [%0], [%1], 16;"
                 :: "r"(dst), "l"(src));
}
#define CP_COMMIT() asm volatile("cp.async.commit_group;" ::: "memory")
#define CP_WAIT0()  asm volatile("cp.async.wait_group 0;" ::: "memory")

// fp32 smem strides (words), ≡ 4 (mod 32): conflict-free b16-trick ldmatrix
#define SD4 260   // 256-wide rows
#define SV4 132   // 128-wide rows
#define SA4 36    // 32-wide rows

// RZ-truncation bias compensation (HMMA truncates fp32 operands to tf32).
#define CF1X 1.000338f
#define CF2X 1.000677f
#define CF3X 1.001015f

// ---------------------------------------------------------------------------
// LA: big-chunk state contribution T^T[j][d] per (bg, j-half). 512 threads.
// (verbatim from R9 — verified at 43us)
// ---------------------------------------------------------------------------
#define A_LGG 0
#define A_WV  2048
#define A_K0  4096
#define A_K1  (A_K0 + 64 * SD4 * 4)
#define A_V0  (A_K1 + 64 * SD4 * 4)
#define A_V1  (A_V0 + 64 * SV4 * 4)
#define A_SMEM (A_V1 + 64 * SV4 * 4)   // 204800

__global__ __launch_bounds__(512, 1) void dr_state(
    const float* __restrict__ K, const float* __restrict__ V,
    const float* __restrict__ beta)
{
    extern __shared__ char sm[];
    float* Lgg = (float*)(sm + A_LGG);
    float* wv  = (float*)(sm + A_WV);
    const uint32_t sb = smem_u32(sm);
    const int bg = blockIdx.x, qj = blockIdx.y;
    const int b = bg >> 3, g2 = bg & 7;
    const int tid = threadIdx.x, wid = tid >> 5, lane = tid & 31;
    const int q = lane & 3, g = lane >> 2;

    const size_t tok0 = (size_t)b * SS + (size_t)g2 * GG;
    const float* Kg = K + tok0 * DD;
    const float* Vg = V + tok0 * DD + qj * 128;

    {
        uint32_t kd = sb + A_K0, vd = sb + A_V0;
        #pragma unroll
        for (int it = 0; it < 8; it++) {
            int idx = it * 512 + tid, row = idx >> 6, c4 = (idx & 63) << 2;
            cp16(kd + (uint32_t)(row * SD4 + c4) * 4, Kg + (size_t)row * DD + c4);
        }
        #pragma unroll
        for (int it = 0; it < 4; it++) {
            int idx = it * 512 + tid, row = idx >> 5, c4 = (idx & 31) << 2;
            cp16(vd + (uint32_t)(row * SV4 + c4) * 4, Vg + (size_t)row * DD + c4);
        }
        CP_COMMIT();
    }

    Lgg[tid] = __logf(fmaxf(beta[tok0 + tid], 1e-30f));
    __syncthreads();
    if (wid == 0) {
        int b0 = lane * 16;
        float s = 0.f;
        #pragma unroll
        for (int u = 0; u < 16; u++) { s += Lgg[b0 + u]; Lgg[b0 + u] = s; }
        float t = s;
        #pragma unroll
        for (int d = 1; d < 32; d <<= 1) {
            float o = __shfl_up_sync(0xFFFFFFFFu, t, d);
            if (lane >= d) t += o;
        }
        float excl = t - s;
        #pragma unroll
        for (int u = 0; u < 16; u++) Lgg[b0 + u] += excl;
    }
    __syncthreads();
    const float lend = Lgg[GG - 1];
    wv[tid] = __expf(lend - Lgg[tid]) * CF1X;
    if (qj == 0) {
        g_Lg[bg * GG + tid] = Lgg[tid];
        if (tid == 0) g_Gamma[bg] = __expf(lend);
    }

    const int jm0 = (wid >> 2) * 32;
    const int i0w = (wid & 3) * 64;

    float acc[2][8][4];
    #pragma unroll
    for (int mt = 0; mt < 2; mt++)
        #pragma unroll
        for (int nt = 0; nt < 8; nt++)
            #pragma unroll
            for (int u = 0; u < 4; u++) acc[mt][nt][u] = 0.f;

    for (int p = 0; p < 8; p++) {
        CP_WAIT0();
        __syncthreads();
        if (p < 7) {
            uint32_t kd = sb + (((p + 1) & 1) ? A_K1 : A_K0);
            uint32_t vd = sb + (((p + 1) & 1) ? A_V1 : A_V0);
            const float* Kn = Kg + (size_t)(p + 1) * 64 * DD;
            const float* Vn = Vg + (size_t)(p + 1) * 64 * DD;
            #pragma unroll
            for (int it = 0; it < 8; it++) {
                int idx = it * 512 + tid, row = idx >> 6, c4 = (idx & 63) << 2;
                cp16(kd + (uint32_t)(row * SD4 + c4) * 4, Kn + (size_t)row * DD + c4);
            }
            #pragma unroll
            for (int it = 0; it < 4; it++) {
                int idx = it * 512 + tid, row = idx >> 5, c4 = (idx & 31) << 2;
                cp16(vd + (uint32_t)(row * SV4 + c4) * 4, Vn + (size_t)row * DD + c4);
            }
            CP_COMMIT();
        }
        const float* Kp = (const float*)(sm + ((p & 1) ? A_K1 : A_K0));
        const float* Vp = (const float*)(sm + ((p & 1) ? A_V1 : A_V0));
        const float* wp = wv + p * 64;

        #pragma unroll
        for (int k0 = 0; k0 < 64; k0 += 8) {
            const int r0 = (k0 + q) * SV4, r4 = (k0 + 4 + q) * SV4;
            const int s0 = (k0 + q) * SD4, s4 = (k0 + 4 + q) * SD4;
            const float w0 = wp[k0 + q], w1 = wp[k0 + 4 + q];
            uint32_t af[2][4], bf[8][2];
            #pragma unroll
            for (int mt = 0; mt < 2; mt++) {
                int jb = jm0 + mt * 16 + g;
                af[mt][0] = __float_as_uint(to_tf32(Vp[r0 + jb] * w0));
                af[mt][1] = __float_as_uint(to_tf32(Vp[r0 + jb + 8] * w0));
                af[mt][2] = __float_as_uint(to_tf32(Vp[r4 + jb] * w1));
                af[mt][3] = __float_as_uint(to_tf32(Vp[r4 + jb + 8] * w1));
            }
            #pragma unroll
            for (int nt = 0; nt < 8; nt++) {
                int db = i0w + nt * 8 + g;
                bf[nt][0] = __float_as_uint(Kp[s0 + db]);
                bf[nt][1] = __float_as_uint(Kp[s4 + db]);
            }
            #pragma unroll
            for (int mt = 0; mt < 2; mt++)
                #pragma unroll
                for (int nt = 0; nt < 8; nt++)
                    mma_tf32(acc[mt][nt], af[mt], bf[nt]);
        }
    }

    float* Sdst = g_S + (size_t)bg * 65536 + (size_t)(qj * 128) * 256;
    #pragma unroll
    for (int mt = 0; mt < 2; mt++)
        #pragma unroll
        for (int nt = 0; nt < 8; nt++) {
            int j = jm0 + mt * 16 + g;
            int d = i0w + nt * 8 + 2 * q;
            float2 v0 = { acc[mt][nt][0], acc[mt][nt][1] };
            float2 v1 = { acc[mt][nt][2], acc[mt][nt][3] };
            *(float2*)(Sdst + (size_t)j * 256 + d) = v0;
            *(float2*)(Sdst + (size_t)(j + 8) * 256 + d) = v1;
        }
}

// ---------------------------------------------------------------------------
// LB: 8-step scan over big-chunk states (in place). (verbatim R9)
// ---------------------------------------------------------------------------
__global__ __launch_bounds__(256) void dr_scan()
{
    const int b = blockIdx.y;
    const size_t e4 = ((size_t)blockIdx.x * 256 + threadIdx.x) * 4;
    float4 h = { 0.f, 0.f, 0.f, 0.f };
    #pragma unroll
    for (int g2 = 0; g2 < NG; g2++) {
        const int bg = b * NG + g2;
        const size_t off = (size_t)bg * 65536 + e4;
        const float gc = g_Gamma[bg];
        float4 s = *(const float4*)(g_S + off);
        *(float4*)(g_S + off) = h;
        h.x = gc * h.x + s.x; h.y = gc * h.y + s.y;
        h.z = gc * h.z + s.z; h.w = gc * h.w + s.w;
    }
}

// ---------------------------------------------------------------------------
// LC: R9 structure (register state [j16][d128]/warp-pair, Q@H via shuffled
// state frags + cross-warp partial reduce) with three cuts:
//   - wv/sg/gamma precomputed for ALL chunks before the loop
//   - 2 barriers per chunk (partials->QK / partials->update fused per warp)
//   - Q@H shuffles hoisted out of the Q-row-tile loop (halved)
// ---------------------------------------------------------------------------
#define C_LGG 0
#define C_WVA 2048
#define C_SGA 4096
#define C_GAM 6144                      // 64 B
#define C_Q0  6272
#define C_Q1  (C_Q0 + 32 * SD4 * 4)     // 39552
#define C_K0  (C_Q1 + 32 * SD4 * 4)     // 72832
#define C_K1  (C_K0 + 32 * SD4 * 4)     // 106112
#define C_V0  (C_K1 + 32 * SD4 * 4)     // 139392
#define C_V1  (C_V0 + 32 * SV4 * 4)     // 156288
#define C_AS  (C_V1 + 32 * SV4 * 4)     // 173184
#define C_R0  (C_AS + 32 * SA4 * 4)     // 177792
#define C_R1  (C_R0 + 32 * SV4 * 4)     // 194688
#define C_SMEM (C_R1 + 32 * SV4 * 4)    // 211584

__global__ __launch_bounds__(512, 1) void dr_out(
    const float* __restrict__ Q, const float* __restrict__ K,
    const float* __restrict__ V, float* __restrict__ O)
{
    extern __shared__ char sm[];
    float* Lgg = (float*)(sm + C_LGG);
    float* wvA = (float*)(sm + C_WVA);
    float* sgA = (float*)(sm + C_SGA);
    float* gamA = (float*)(sm + C_GAM);
    float* Asf = (float*)(sm + C_AS);
    float* R0f = (float*)(sm + C_R0);
    float* R1f = (float*)(sm + C_R1);
    const uint32_t sb = smem_u32(sm);

    const int bg = blockIdx.x, jh = blockIdx.y;
    const int b = bg >> 3, g2 = bg & 7;
    const int tid = threadIdx.x, wid = tid >> 5, lane = tid & 31;
    const int q = lane & 3, g = lane >> 2;
    const int rA = lane & 15, cA = (lane >> 4) * 4;
    const int rB = lane & 7,  cB = ((lane >> 3) & 1) * 4;

    const size_t tok0 = (size_t)b * SS + (size_t)g2 * GG;
    const float* Qg = Q + tok0 * DD;
    const float* Kg = K + tok0 * DD;
    const float* Vg = V + tok0 * DD + jh * 128;

    // issue chunk 0 (buffers don't overlap table region)
    {
        uint32_t qd = sb + C_Q0, kd = sb + C_K0, vd = sb + C_V0;
        #pragma unroll
        for (int it = 0; it < 4; it++) {
            int idx = it * 512 + tid, row = idx >> 6, c4 = (idx & 63) << 2;
            cp16(qd + (uint32_t)(row * SD4 + c4) * 4, Qg + (size_t)row * DD + c4);
            cp16(kd + (uint32_t)(row * SD4 + c4) * 4, Kg + (size_t)row * DD + c4);
        }
        #pragma unroll
        for (int it = 0; it < 2; it++) {
            int idx = it * 512 + tid, row = idx >> 5, c4 = (idx & 31) << 2;
            cp16(vd + (uint32_t)(row * SV4 + c4) * 4, Vg + (size_t)row * DD + c4);
        }
        CP_COMMIT();
    }

    Lgg[tid] = g_Lg[bg * GG + tid];
    __syncthreads();                        // Lgg visible

    // precompute per-chunk tables (removes exp from the loop critical path)
    {
        int c = tid >> 5, p = tid & 31;
        float baseL = c ? Lgg[c * CI - 1] : 0.f;
        float lendI = Lgg[c * CI + CI - 1];
        float lt = Lgg[c * CI + p];
        wvA[tid] = __expf(lendI - lt) * CF1X;
        sgA[tid] = __expf(lt - baseL) * CF2X;
        if (tid < NIC)
            gamA[tid] = __expf(Lgg[tid * CI + CI - 1] -
                               (tid ? Lgg[tid * CI - 1] : 0.f));
    }

    // state regs: warp tile [j 16][d 128]; pairs (2w,2w+1) split d.
    const int jm0 = (wid >> 1) * 16;
    const int nb0 = (wid & 1) * 128;
    float st[16][4];
    {
        const float* Sg = g_S + (size_t)bg * 65536 + (size_t)(jh * 128) * 256;
        #pragma unroll
        for (int nt = 0; nt < 16; nt++) {
            int d = nb0 + nt * 8 + 2 * q;
            float2 lo = *(const float2*)(Sg + (size_t)(jm0 + g) * 256 + d);
            float2 hi = *(const float2*)(Sg + (size_t)(jm0 + 8 + g) * 256 + d);
            st[nt][0] = lo.x; st[nt][1] = lo.y;
            st[nt][2] = hi.x; st[nt][3] = hi.y;
        }
    }

    const int srcq = (lane & ~3) | (q >> 1);
    const uint32_t asb = sb + C_AS;

    for (int ic = 0; ic < NIC; ic++) {
        const int icb = ic * CI;
        CP_WAIT0();
        __syncthreads();                    // B0: buffers ready, prior readers done
        if (ic < NIC - 1) {
            uint32_t qd = sb + (((ic + 1) & 1) ? C_Q1 : C_Q0);
            uint32_t kd = sb + (((ic + 1) & 1) ? C_K1 : C_K0);
            uint32_t vd = sb + (((ic + 1) & 1) ? C_V1 : C_V0);
            const float* Qn = Qg + (size_t)(icb + CI) * DD;
            const float* Kn = Kg + (size_t)(icb + CI) * DD;
            const float* Vn = Vg + (size_t)(icb + CI) * DD;
            #pragma unroll
            for (int it = 0; it < 4; it++) {
                int idx = it * 512 + tid, row = idx >> 6, c4 = (idx & 63) << 2;
                cp16(qd + (uint32_t)(row * SD4 + c4) * 4, Qn + (size_t)row * DD + c4);
                cp16(kd + (uint32_t)(row * SD4 + c4) * 4, Kn + (size_t)row * DD + c4);
            }
            #pragma unroll
            for (int it = 0; it < 2; it++) {
                int idx = it * 512 + tid, row = idx >> 5, c4 = (idx & 31) << 2;
                cp16(vd + (uint32_t)(row * SV4 + c4) * 4, Vn + (size_t)row * DD + c4);
            }
            CP_COMMIT();
        }

        const float* wv = wvA + icb;
        const float* sg = sgA + icb;
        const float gamma = gamA[ic];
        const uint32_t qbc = sb + ((ic & 1) ? C_Q1 : C_Q0);
        const uint32_t kbc = sb + ((ic & 1) ? C_K1 : C_K0);
        const float* Vc = (const float*)(sm + ((ic & 1) ? C_V1 : C_V0));
        const float* Kc = (const float*)(sm + ((ic & 1) ? C_K1 : C_K0));

        // ---- Phase A (all warps): Q@H partials, shuffles hoisted ----
        float* Rb = (wid & 1) ? R1f : R0f;
        {
            float accP[2][2][4];
            #pragma unroll
            for (int it = 0; it < 2; it++)
                #pragma unroll
                for (int nb = 0; nb < 2; nb++)
                    #pragma unroll
                    for (int u = 0; u < 4; u++) accP[it][nb][u] = 0.f;
            #pragma unroll
            for (int nt = 0; nt < 16; nt++) {
                float s00 = __shfl_sync(0xFFFFFFFFu, st[nt][0], srcq);
                float s01 = __shfl_sync(0xFFFFFFFFu, st[nt][1], srcq);
                float s02 = __shfl_sync(0xFFFFFFFFu, st[nt][0], srcq + 2);
                float s03 = __shfl_sync(0xFFFFFFFFu, st[nt][1], srcq + 2);
                float s10 = __shfl_sync(0xFFFFFFFFu, st[nt][2], srcq);
                float s11 = __shfl_sync(0xFFFFFFFFu, st[nt][3], srcq);
                float s12 = __shfl_sync(0xFFFFFFFFu, st[nt][2], srcq + 2);
                float s13 = __shfl_sync(0xFFFFFFFFu, st[nt][3], srcq + 2);
                uint32_t blo[2] = { __float_as_uint((q & 1) ? s01 : s00),
                                    __float_as_uint((q & 1) ? s03 : s02) };
                uint32_t bhi[2] = { __float_as_uint((q & 1) ? s11 : s10),
                                    __float_as_uint((q & 1) ? s13 : s12) };
                #pragma unroll
                for (int it = 0; it < 2; it++) {
                    uint32_t af[4];
                    ldmx4(af, qbc + (uint32_t)((it * 16 + rA) * SD4 + nb0 + nt * 8 + cA) * 4);
                    mma_tf32(accP[it][0], af, blo);
                    mma_tf32(accP[it][1], af, bhi);
                }
            }
            #pragma unroll
            for (int it = 0; it < 2; it++)
                #pragma unroll
                for (int nb = 0; nb < 2; nb++) {
                    int jc = jm0 + nb * 8 + 2 * q;
                    *(float2*)(Rb + (it * 16 + g) * SV4 + jc) =
                        make_float2(accP[it][nb][0], accP[it][nb][1]);
                    *(float2*)(Rb + (it * 16 + 8 + g) * SV4 + jc) =
                        make_float2(accP[it][nb][2], accP[it][nb][3]);
                }
        }

        if (!(wid & 1)) {
            // even warps continue: QK^T -> masked decayed A
            int e = wid >> 1;
            int i0q = (e >> 2) * 16, t0q = (e & 3) * 8;
            float a1[4] = { 0.f, 0.f, 0.f, 0.f };
            #pragma unroll
            for (int k0 = 0; k0 < 256; k0 += 8) {
                uint32_t af[4], bf[2];
                ldmx4(af, qbc + (uint32_t)((i0q + rA) * SD4 + k0 + cA) * 4);
                ldmx2(bf, kbc + (uint32_t)((t0q + rB) * SD4 + k0 + cB) * 4);
                mma_tf32(a1, af, bf);
            }
            int ia = i0q + g, ib2 = ia + 8, t = t0q + 2 * q;
            float lia = Lgg[icb + ia], lib = Lgg[icb + ib2];
            float lt0 = Lgg[icb + t], lt1 = Lgg[icb + t + 1];
            float f00 = (t     <= ia)  ? __expf(lia - lt0) * CF3X : 0.f;
            float f01 = (t + 1 <= ia)  ? __expf(lia - lt1) * CF3X : 0.f;
            float f10 = (t     <= ib2) ? __expf(lib - lt0) * CF3X : 0.f;
            float f11 = (t + 1 <= ib2) ? __expf(lib - lt1) * CF3X : 0.f;
            *(float2*)(Asf + ia * SA4 + t) =
                make_float2(to_tf32(a1[0] * f00), to_tf32(a1[1] * f01));
            *(float2*)(Asf + ib2 * SA4 + t) =
                make_float2(to_tf32(a1[2] * f10), to_tf32(a1[3] * f11));
        } else {
            // odd warps continue: state update
            #pragma unroll
            for (int nt = 0; nt < 16; nt++) {
                st[nt][0] *= gamma; st[nt][1] *= gamma;
                st[nt][2] *= gamma; st[nt][3] *= gamma;
            }
            #pragma unroll
            for (int k0 = 0; k0 < CI; k0 += 8) {
                const int r0 = (k0 + q) * SV4, r4 = (k0 + 4 + q) * SV4;
                const int s0 = (k0 + q) * SD4, s4 = (k0 + 4 + q) * SD4;
                const float w0 = wv[k0 + q], w1 = wv[k0 + 4 + q];
                uint32_t af[4];
                af[0] = __float_as_uint(to_tf32(Vc[r0 + jm0 + g] * w0));
                af[1] = __float_as_uint(to_tf32(Vc[r0 + jm0 + 8 + g] * w0));
                af[2] = __float_as_uint(to_tf32(Vc[r4 + jm0 + g] * w1));
                af[3] = __float_as_uint(to_tf32(Vc[r4 + jm0 + 8 + g] * w1));
                #pragma unroll
                for (int nt = 0; nt < 16; nt++) {
                    int d0 = nb0 + nt * 8 + g;
                    uint32_t bf[2] = { __float_as_uint(Kc[s0 + d0]),
                                       __float_as_uint(Kc[s4 + d0]) };
                    mma_tf32(st[nt], af, bf);
                }
            }
        }
        __syncthreads();                    // B1: As + partials visible

        if (wid & 1) {
            // odd warps: combine partials, A@V, store O
            #pragma unroll
            for (int it = 0; it < 2; it++) {
                float sa = sg[it * 16 + g], sb2 = sg[it * 16 + 8 + g];
                float acc[2][4];
                #pragma unroll
                for (int nb = 0; nb < 2; nb++) {
                    int jc = jm0 + nb * 8 + 2 * q;
                    float2 a0 = *(float2*)(R1f + (it * 16 + g) * SV4 + jc);
                    float2 b0 = *(float2*)(R0f + (it * 16 + g) * SV4 + jc);
                    float2 a1 = *(float2*)(R1f + (it * 16 + 8 + g) * SV4 + jc);
                    float2 b1 = *(float2*)(R0f + (it * 16 + 8 + g) * SV4 + jc);
                    acc[nb][0] = sa * (a0.x + b0.x);
                    acc[nb][1] = sa * (a0.y + b0.y);
                    acc[nb][2] = sb2 * (a1.x + b1.x);
                    acc[nb][3] = sb2 * (a1.y + b1.y);
                }
                #pragma unroll
                for (int k0 = 0; k0 < CI; k0 += 8) {
                    uint32_t af[4];
                    ldmx4(af, asb + (uint32_t)((it * 16 + rA) * SA4 + k0 + cA) * 4);
                    #pragma unroll
                    for (int nb = 0; nb < 2; nb++) {
                        int jc = jm0 + nb * 8 + g;
                        uint32_t bf[2] = {
                            __float_as_uint(Vc[(k0 + q) * SV4 + jc]),
                            __float_as_uint(Vc[(k0 + 4 + q) * SV4 + jc]) };
                        mma_tf32(acc[nb], af, bf);
                    }
                }
                size_t ro0 = (tok0 + icb + it * 16 + g) * DD + jh * 128;
                size_t ro1 = (tok0 + icb + it * 16 + 8 + g) * DD + jh * 128;
                #pragma unroll
                for (int nb = 0; nb < 2; nb++) {
                    int jc = jm0 + nb * 8 + 2 * q;
                    *(float2*)(O + ro0 + jc) = make_float2(acc[nb][0], acc[nb][1]);
                    *(float2*)(O + ro1 + jc) = make_float2(acc[nb][2], acc[nb][3]);
                }
            }
        } else {
            // even warps: state update
            #pragma unroll
            for (int nt = 0; nt < 16; nt++) {
                st[nt][0] *= gamma; st[nt][1] *= gamma;
                st[nt][2] *= gamma; st[nt][3] *= gamma;
            }
            #pragma unroll
            for (int k0 = 0; k0 < CI; k0 += 8) {
                const int r0 = (k0 + q) * SV4, r4 = (k0 + 4 + q) * SV4;
                const int s0 = (k0 + q) * SD4, s4 = (k0 + 4 + q) * SD4;
                const float w0 = wv[k0 + q], w1 = wv[k0 + 4 + q];
                uint32_t af[4];
                af[0] = __float_as_uint(to_tf32(Vc[r0 + jm0 + g] * w0));
                af[1] = __float_as_uint(to_tf32(Vc[r0 + jm0 + 8 + g] * w0));
                af[2] = __float_as_uint(to_tf32(Vc[r4 + jm0 + g] * w1));
                af[3] = __float_as_uint(to_tf32(Vc[r4 + jm0 + 8 + g] * w1));
                #pragma unroll
                for (int nt = 0; nt < 16; nt++) {
                    int d0 = nb0 + nt * 8 + g;
                    uint32_t bf[2] = { __float_as_uint(Kc[s0 + d0]),
                                       __float_as_uint(Kc[s4 + d0]) };
                    mma_tf32(st[nt], af, bf);
                }
            }
        }
    }
}

// ---------------------------------------------------------------------------
extern "C" void kernel_launch(void* const* d_in, const int* in_sizes, int n_in,
                              void* d_out, int out_size)
{
    const float* q    = (const float*)d_in[0];
    const float* k    = (const float*)d_in[1];
    const float* v    = (const float*)d_in[2];
    const float* beta = (const float*)d_in[3];
    float* out = (float*)d_out;
    (void)in_sizes; (void)n_in; (void)out_size;

    cudaFuncSetAttribute(dr_state, cudaFuncAttributeMaxDynamicSharedMemorySize, A_SMEM);
    cudaFuncSetAttribute(dr_out,   cudaFuncAttributeMaxDynamicSharedMemorySize, C_SMEM);

    dr_state<<<dim3(NBG, 2), 512, A_SMEM>>>(k, v, beta);
    dr_scan<<<dim3(64, BB), 256>>>();
    dr_out<<<dim3(NBG, 2), 512, C_SMEM>>>(q, k, v, out);
}

// round 12
// speedup vs baseline: 1.2512x; 1.0448x over previous
#include <cuda_runtime.h>
#include <cstdint>
#include <cstddef>

#define BB 8
#define SS 4096
#define DD 256
#define GG 512      // big chunk
#define NG 8        // big chunks per batch
#define NBG 64      // total big chunks
#define CI 32       // inner chunk
#define NIC 16      // inner chunks per big chunk

// Scratch: per-big-chunk state^T [bg][j][d]; LB converts in place to the
// state ENTERING each big chunk (16.8 MB).
__device__ float g_S[(size_t)NBG * DD * DD];
__device__ float g_Lg[NBG * GG];
__device__ float g_Gamma[NBG];

// ---------------------------------------------------------------------------
// Helpers
// ---------------------------------------------------------------------------
__device__ __forceinline__ uint32_t smem_u32(const void* p) {
    uint32_t a;
    asm("{ .reg .u64 t; cvta.to.shared.u64 t, %1; cvt.u32.u64 %0, t; }"
        : "=r"(a) : "l"(p));
    return a;
}

__device__ __forceinline__ float to_tf32(float f) {
    uint32_t r;
    asm("cvt.rna.tf32.f32 %0, %1;" : "=r"(r) : "f"(f));
    return __uint_as_float(r);
}

__device__ __forceinline__ void mma_tf32(float c[4], const uint32_t a[4],
                                         const uint32_t b[2]) {
    asm volatile(
        "mma.sync.aligned.m16n8k8.row.col.f32.tf32.tf32.f32 "
        "{%0,%1,%2,%3}, {%4,%5,%6,%7}, {%8,%9}, {%0,%1,%2,%3};"
        : "+f"(c[0]), "+f"(c[1]), "+f"(c[2]), "+f"(c[3])
        : "r"(a[0]), "r"(a[1]), "r"(a[2]), "r"(a[3]), "r"(b[0]), "r"(b[1]));
}

__device__ __forceinline__ void ldmx4(uint32_t r[4], uint32_t a) {
    asm volatile("ldmatrix.sync.aligned.m8n8.x4.shared.b16 {%0,%1,%2,%3}, [%4];"
                 : "=r"(r[0]), "=r"(r[1]), "=r"(r[2]), "=r"(r[3]) : "r"(a));
}
__device__ __forceinline__ void ldmx2(uint32_t r[2], uint32_t a) {
    asm volatile("ldmatrix.sync.aligned.m8n8.x2.shared.b16 {%0,%1}, [%2];"
                 : "=r"(r[0]), "=r"(r[1]) : "r"(a));
}

__device__ __forceinline__ void cp16(uint32_t dst, const void* src) {
    asm volatile("cp.async.cg.shared.global [%0], [%1], 16;"
                 :: "r"(dst), "l"(src));
}
#define CP_COMMIT() asm volatile("cp.async.commit_group;" ::: "memory")
#define CP_WAIT0()  asm volatile("cp.async.wait_group 0;" ::: "memory")

// fp32 smem strides (words), ≡ 4 (mod 32): conflict-free b16-trick ldmatrix
#define SD4 260   // 256-wide rows
#define SV4 132   // 128-wide rows
#define SA4 36    // 32-wide rows

// RZ-truncation bias compensation (HMMA truncates fp32 operands to tf32).
#define CF1X 1.000338f
#define CF2X 1.000677f
#define CF3X 1.001015f

// Split state-update: st = (first part: already gamma-scaled) + K^T (wV)
// over k0 in [B, E). Compile-time bounds keep full unrolling.
template<int B, int E>
__device__ __forceinline__ void upd_part(
    float (&st)[16][4], const float* __restrict__ Vc,
    const float* __restrict__ Kc, const float* __restrict__ wv,
    int jm0, int nb0, int g, int q)
{
    #pragma unroll
    for (int k0 = B; k0 < E; k0 += 8) {
        const int r0 = (k0 + q) * SV4, r4 = (k0 + 4 + q) * SV4;
        const int s0 = (k0 + q) * SD4, s4 = (k0 + 4 + q) * SD4;
        const float w0 = wv[k0 + q], w1 = wv[k0 + 4 + q];
        uint32_t af[4];
        af[0] = __float_as_uint(to_tf32(Vc[r0 + jm0 + g] * w0));
        af[1] = __float_as_uint(to_tf32(Vc[r0 + jm0 + 8 + g] * w0));
        af[2] = __float_as_uint(to_tf32(Vc[r4 + jm0 + g] * w1));
        af[3] = __float_as_uint(to_tf32(Vc[r4 + jm0 + 8 + g] * w1));
        #pragma unroll
        for (int nt = 0; nt < 16; nt++) {
            int d0 = nb0 + nt * 8 + g;
            uint32_t bf[2] = { __float_as_uint(Kc[s0 + d0]),
                               __float_as_uint(Kc[s4 + d0]) };
            mma_tf32(st[nt], af, bf);
        }
    }
}

// ---------------------------------------------------------------------------
// LA: big-chunk state contribution T^T[j][d] per (bg, j-half). 512 threads.
// (verbatim — verified at 43us)
// ---------------------------------------------------------------------------
#define A_LGG 0
#define A_WV  2048
#define A_K0  4096
#define A_K1  (A_K0 + 64 * SD4 * 4)
#define A_V0  (A_K1 + 64 * SD4 * 4)
#define A_V1  (A_V0 + 64 * SV4 * 4)
#define A_SMEM (A_V1 + 64 * SV4 * 4)   // 204800

__global__ __launch_bounds__(512, 1) void dr_state(
    const float* __restrict__ K, const float* __restrict__ V,
    const float* __restrict__ beta)
{
    extern __shared__ char sm[];
    float* Lgg = (float*)(sm + A_LGG);
    float* wv  = (float*)(sm + A_WV);
    const uint32_t sb = smem_u32(sm);
    const int bg = blockIdx.x, qj = blockIdx.y;
    const int b = bg >> 3, g2 = bg & 7;
    const int tid = threadIdx.x, wid = tid >> 5, lane = tid & 31;
    const int q = lane & 3, g = lane >> 2;

    const size_t tok0 = (size_t)b * SS + (size_t)g2 * GG;
    const float* Kg = K + tok0 * DD;
    const float* Vg = V + tok0 * DD + qj * 128;

    {
        uint32_t kd = sb + A_K0, vd = sb + A_V0;
        #pragma unroll
        for (int it = 0; it < 8; it++) {
            int idx = it * 512 + tid, row = idx >> 6, c4 = (idx & 63) << 2;
            cp16(kd + (uint32_t)(row * SD4 + c4) * 4, Kg + (size_t)row * DD + c4);
        }
        #pragma unroll
        for (int it = 0; it < 4; it++) {
            int idx = it * 512 + tid, row = idx >> 5, c4 = (idx & 31) << 2;
            cp16(vd + (uint32_t)(row * SV4 + c4) * 4, Vg + (size_t)row * DD + c4);
        }
        CP_COMMIT();
    }

    Lgg[tid] = __logf(fmaxf(beta[tok0 + tid], 1e-30f));
    __syncthreads();
    if (wid == 0) {
        int b0 = lane * 16;
        float s = 0.f;
        #pragma unroll
        for (int u = 0; u < 16; u++) { s += Lgg[b0 + u]; Lgg[b0 + u] = s; }
        float t = s;
        #pragma unroll
        for (int d = 1; d < 32; d <<= 1) {
            float o = __shfl_up_sync(0xFFFFFFFFu, t, d);
            if (lane >= d) t += o;
        }
        float excl = t - s;
        #pragma unroll
        for (int u = 0; u < 16; u++) Lgg[b0 + u] += excl;
    }
    __syncthreads();
    const float lend = Lgg[GG - 1];
    wv[tid] = __expf(lend - Lgg[tid]) * CF1X;
    if (qj == 0) {
        g_Lg[bg * GG + tid] = Lgg[tid];
        if (tid == 0) g_Gamma[bg] = __expf(lend);
    }

    const int jm0 = (wid >> 2) * 32;
    const int i0w = (wid & 3) * 64;

    float acc[2][8][4];
    #pragma unroll
    for (int mt = 0; mt < 2; mt++)
        #pragma unroll
        for (int nt = 0; nt < 8; nt++)
            #pragma unroll
            for (int u = 0; u < 4; u++) acc[mt][nt][u] = 0.f;

    for (int p = 0; p < 8; p++) {
        CP_WAIT0();
        __syncthreads();
        if (p < 7) {
            uint32_t kd = sb + (((p + 1) & 1) ? A_K1 : A_K0);
            uint32_t vd = sb + (((p + 1) & 1) ? A_V1 : A_V0);
            const float* Kn = Kg + (size_t)(p + 1) * 64 * DD;
            const float* Vn = Vg + (size_t)(p + 1) * 64 * DD;
            #pragma unroll
            for (int it = 0; it < 8; it++) {
                int idx = it * 512 + tid, row = idx >> 6, c4 = (idx & 63) << 2;
                cp16(kd + (uint32_t)(row * SD4 + c4) * 4, Kn + (size_t)row * DD + c4);
            }
            #pragma unroll
            for (int it = 0; it < 4; it++) {
                int idx = it * 512 + tid, row = idx >> 5, c4 = (idx & 31) << 2;
                cp16(vd + (uint32_t)(row * SV4 + c4) * 4, Vn + (size_t)row * DD + c4);
            }
            CP_COMMIT();
        }
        const float* Kp = (const float*)(sm + ((p & 1) ? A_K1 : A_K0));
        const float* Vp = (const float*)(sm + ((p & 1) ? A_V1 : A_V0));
        const float* wp = wv + p * 64;

        #pragma unroll
        for (int k0 = 0; k0 < 64; k0 += 8) {
            const int r0 = (k0 + q) * SV4, r4 = (k0 + 4 + q) * SV4;
            const int s0 = (k0 + q) * SD4, s4 = (k0 + 4 + q) * SD4;
            const float w0 = wp[k0 + q], w1 = wp[k0 + 4 + q];
            uint32_t af[2][4], bf[8][2];
            #pragma unroll
            for (int mt = 0; mt < 2; mt++) {
                int jb = jm0 + mt * 16 + g;
                af[mt][0] = __float_as_uint(to_tf32(Vp[r0 + jb] * w0));
                af[mt][1] = __float_as_uint(to_tf32(Vp[r0 + jb + 8] * w0));
                af[mt][2] = __float_as_uint(to_tf32(Vp[r4 + jb] * w1));
                af[mt][3] = __float_as_uint(to_tf32(Vp[r4 + jb + 8] * w1));
            }
            #pragma unroll
            for (int nt = 0; nt < 8; nt++) {
                int db = i0w + nt * 8 + g;
                bf[nt][0] = __float_as_uint(Kp[s0 + db]);
                bf[nt][1] = __float_as_uint(Kp[s4 + db]);
            }
            #pragma unroll
            for (int mt = 0; mt < 2; mt++)
                #pragma unroll
                for (int nt = 0; nt < 8; nt++)
                    mma_tf32(acc[mt][nt], af[mt], bf[nt]);
        }
    }

    float* Sdst = g_S + (size_t)bg * 65536 + (size_t)(qj * 128) * 256;
    #pragma unroll
    for (int mt = 0; mt < 2; mt++)
        #pragma unroll
        for (int nt = 0; nt < 8; nt++) {
            int j = jm0 + mt * 16 + g;
            int d = i0w + nt * 8 + 2 * q;
            float2 v0 = { acc[mt][nt][0], acc[mt][nt][1] };
            float2 v1 = { acc[mt][nt][2], acc[mt][nt][3] };
            *(float2*)(Sdst + (size_t)j * 256 + d) = v0;
            *(float2*)(Sdst + (size_t)(j + 8) * 256 + d) = v1;
        }
}

// ---------------------------------------------------------------------------
// LB: 8-step scan over big-chunk states (in place). (verbatim)
// ---------------------------------------------------------------------------
__global__ __launch_bounds__(256) void dr_scan()
{
    const int b = blockIdx.y;
    const size_t e4 = ((size_t)blockIdx.x * 256 + threadIdx.x) * 4;
    float4 h = { 0.f, 0.f, 0.f, 0.f };
    #pragma unroll
    for (int g2 = 0; g2 < NG; g2++) {
        const int bg = b * NG + g2;
        const size_t off = (size_t)bg * 65536 + e4;
        const float gc = g_Gamma[bg];
        float4 s = *(const float4*)(g_S + off);
        *(float4*)(g_S + off) = h;
        h.x = gc * h.x + s.x; h.y = gc * h.y + s.y;
        h.z = gc * h.z + s.z; h.w = gc * h.w + s.w;
    }
}

// ---------------------------------------------------------------------------
// LC: R11 structure with the state update SPLIT across phases by warp
// parity so both phases are issue-balanced:
//   Phase A: even QH + upd[0,8) + QK (112 mma); odd QH + upd[0,24) (112)
//   Phase B: even upd[8,32) (48);  odd upd[24,32) + A@V + O stores (~40)
// ---------------------------------------------------------------------------
#define C_LGG 0
#define C_WVA 2048
#define C_SGA 4096
#define C_GAM 6144                      // 64 B
#define C_Q0  6272
#define C_Q1  (C_Q0 + 32 * SD4 * 4)     // 39552
#define C_K0  (C_Q1 + 32 * SD4 * 4)     // 72832
#define C_K1  (C_K0 + 32 * SD4 * 4)     // 106112
#define C_V0  (C_K1 + 32 * SD4 * 4)     // 139392
#define C_V1  (C_V0 + 32 * SV4 * 4)     // 156288
#define C_AS  (C_V1 + 32 * SV4 * 4)     // 173184
#define C_R0  (C_AS + 32 * SA4 * 4)     // 177792
#define C_R1  (C_R0 + 32 * SV4 * 4)     // 194688
#define C_SMEM (C_R1 + 32 * SV4 * 4)    // 211584

__global__ __launch_bounds__(512, 1) void dr_out(
    const float* __restrict__ Q, const float* __restrict__ K,
    const float* __restrict__ V, float* __restrict__ O)
{
    extern __shared__ char sm[];
    float* Lgg = (float*)(sm + C_LGG);
    float* wvA = (float*)(sm + C_WVA);
    float* sgA = (float*)(sm + C_SGA);
    float* gamA = (float*)(sm + C_GAM);
    float* Asf = (float*)(sm + C_AS);
    float* R0f = (float*)(sm + C_R0);
    float* R1f = (float*)(sm + C_R1);
    const uint32_t sb = smem_u32(sm);

    const int bg = blockIdx.x, jh = blockIdx.y;
    const int b = bg >> 3, g2 = bg & 7;
    const int tid = threadIdx.x, wid = tid >> 5, lane = tid & 31;
    const int q = lane & 3, g = lane >> 2;
    const int rA = lane & 15, cA = (lane >> 4) * 4;
    const int rB = lane & 7,  cB = ((lane >> 3) & 1) * 4;

    const size_t tok0 = (size_t)b * SS + (size_t)g2 * GG;
    const float* Qg = Q + tok0 * DD;
    const float* Kg = K + tok0 * DD;
    const float* Vg = V + tok0 * DD + jh * 128;

    // issue chunk 0
    {
        uint32_t qd = sb + C_Q0, kd = sb + C_K0, vd = sb + C_V0;
        #pragma unroll
        for (int it = 0; it < 4; it++) {
            int idx = it * 512 + tid, row = idx >> 6, c4 = (idx & 63) << 2;
            cp16(qd + (uint32_t)(row * SD4 + c4) * 4, Qg + (size_t)row * DD + c4);
            cp16(kd + (uint32_t)(row * SD4 + c4) * 4, Kg + (size_t)row * DD + c4);
        }
        #pragma unroll
        for (int it = 0; it < 2; it++) {
            int idx = it * 512 + tid, row = idx >> 5, c4 = (idx & 31) << 2;
            cp16(vd + (uint32_t)(row * SV4 + c4) * 4, Vg + (size_t)row * DD + c4);
        }
        CP_COMMIT();
    }

    Lgg[tid] = g_Lg[bg * GG + tid];
    __syncthreads();                        // Lgg visible

    // precompute per-chunk tables
    {
        int c = tid >> 5, p = tid & 31;
        float baseL = c ? Lgg[c * CI - 1] : 0.f;
        float lendI = Lgg[c * CI + CI - 1];
        float lt = Lgg[c * CI + p];
        wvA[tid] = __expf(lendI - lt) * CF1X;
        sgA[tid] = __expf(lt - baseL) * CF2X;
        if (tid < NIC)
            gamA[tid] = __expf(Lgg[tid * CI + CI - 1] -
                               (tid ? Lgg[tid * CI - 1] : 0.f));
    }

    // state regs: warp tile [j 16][d 128]; pairs (2w,2w+1) split d.
    const int jm0 = (wid >> 1) * 16;
    const int nb0 = (wid & 1) * 128;
    float st[16][4];
    {
        const float* Sg = g_S + (size_t)bg * 65536 + (size_t)(jh * 128) * 256;
        #pragma unroll
        for (int nt = 0; nt < 16; nt++) {
            int d = nb0 + nt * 8 + 2 * q;
            float2 lo = *(const float2*)(Sg + (size_t)(jm0 + g) * 256 + d);
            float2 hi = *(const float2*)(Sg + (size_t)(jm0 + 8 + g) * 256 + d);
            st[nt][0] = lo.x; st[nt][1] = lo.y;
            st[nt][2] = hi.x; st[nt][3] = hi.y;
        }
    }

    const int srcq = (lane & ~3) | (q >> 1);
    const uint32_t asb = sb + C_AS;

    for (int ic = 0; ic < NIC; ic++) {
        const int icb = ic * CI;
        CP_WAIT0();
        __syncthreads();                    // B0: buffers ready, prior readers done
        if (ic < NIC - 1) {
            uint32_t qd = sb + (((ic + 1) & 1) ? C_Q1 : C_Q0);
            uint32_t kd = sb + (((ic + 1) & 1) ? C_K1 : C_K0);
            uint32_t vd = sb + (((ic + 1) & 1) ? C_V1 : C_V0);
            const float* Qn = Qg + (size_t)(icb + CI) * DD;
            const float* Kn = Kg + (size_t)(icb + CI) * DD;
            const float* Vn = Vg + (size_t)(icb + CI) * DD;
            #pragma unroll
            for (int it = 0; it < 4; it++) {
                int idx = it * 512 + tid, row = idx >> 6, c4 = (idx & 63) << 2;
                cp16(qd + (uint32_t)(row * SD4 + c4) * 4, Qn + (size_t)row * DD + c4);
                cp16(kd + (uint32_t)(row * SD4 + c4) * 4, Kn + (size_t)row * DD + c4);
            }
            #pragma unroll
            for (int it = 0; it < 2; it++) {
                int idx = it * 512 + tid, row = idx >> 5, c4 = (idx & 31) << 2;
                cp16(vd + (uint32_t)(row * SV4 + c4) * 4, Vn + (size_t)row * DD + c4);
            }
            CP_COMMIT();
        }

        const float* wv = wvA + icb;
        const float* sg = sgA + icb;
        const float gamma = gamA[ic];
        const uint32_t qbc = sb + ((ic & 1) ? C_Q1 : C_Q0);
        const uint32_t kbc = sb + ((ic & 1) ? C_K1 : C_K0);
        const float* Vc = (const float*)(sm + ((ic & 1) ? C_V1 : C_V0));
        const float* Kc = (const float*)(sm + ((ic & 1) ? C_K1 : C_K0));

        // ---- Phase A (all warps): Q@H partials (pre-update state) ----
        float* Rb = (wid & 1) ? R1f : R0f;
        {
            float accP[2][2][4];
            #pragma unroll
            for (int it = 0; it < 2; it++)
                #pragma unroll
                for (int nb = 0; nb < 2; nb++)
                    #pragma unroll
                    for (int u = 0; u < 4; u++) accP[it][nb][u] = 0.f;
            #pragma unroll
            for (int nt = 0; nt < 16; nt++) {
                float s00 = __shfl_sync(0xFFFFFFFFu, st[nt][0], srcq);
                float s01 = __shfl_sync(0xFFFFFFFFu, st[nt][1], srcq);
                float s02 = __shfl_sync(0xFFFFFFFFu, st[nt][0], srcq + 2);
                float s03 = __shfl_sync(0xFFFFFFFFu, st[nt][1], srcq + 2);
                float s10 = __shfl_sync(0xFFFFFFFFu, st[nt][2], srcq);
                float s11 = __shfl_sync(0xFFFFFFFFu, st[nt][3], srcq);
                float s12 = __shfl_sync(0xFFFFFFFFu, st[nt][2], srcq + 2);
                float s13 = __shfl_sync(0xFFFFFFFFu, st[nt][3], srcq + 2);
                uint32_t blo[2] = { __float_as_uint((q & 1) ? s01 : s00),
                                    __float_as_uint((q & 1) ? s03 : s02) };
                uint32_t bhi[2] = { __float_as_uint((q & 1) ? s11 : s10),
                                    __float_as_uint((q & 1) ? s13 : s12) };
                #pragma unroll
                for (int it = 0; it < 2; it++) {
                    uint32_t af[4];
                    ldmx4(af, qbc + (uint32_t)((it * 16 + rA) * SD4 + nb0 + nt * 8 + cA) * 4);
                    mma_tf32(accP[it][0], af, blo);
                    mma_tf32(accP[it][1], af, bhi);
                }
            }
            #pragma unroll
            for (int it = 0; it < 2; it++)
                #pragma unroll
                for (int nb = 0; nb < 2; nb++) {
                    int jc = jm0 + nb * 8 + 2 * q;
                    *(float2*)(Rb + (it * 16 + g) * SV4 + jc) =
                        make_float2(accP[it][nb][0], accP[it][nb][1]);
                    *(float2*)(Rb + (it * 16 + 8 + g) * SV4 + jc) =
                        make_float2(accP[it][nb][2], accP[it][nb][3]);
                }
        }

        // gamma-scale state (both parities; update halves follow)
        #pragma unroll
        for (int nt = 0; nt < 16; nt++) {
            st[nt][0] *= gamma; st[nt][1] *= gamma;
            st[nt][2] *= gamma; st[nt][3] *= gamma;
        }

        if (!(wid & 1)) {
            // even: small update slice, then QK^T -> masked decayed A
            upd_part<0, 8>(st, Vc, Kc, wv, jm0, nb0, g, q);

            int e = wid >> 1;
            int i0q = (e >> 2) * 16, t0q = (e & 3) * 8;
            float a1[4] = { 0.f, 0.f, 0.f, 0.f };
            #pragma unroll
            for (int k0 = 0; k0 < 256; k0 += 8) {
                uint32_t af[4], bf[2];
                ldmx4(af, qbc + (uint32_t)((i0q + rA) * SD4 + k0 + cA) * 4);
                ldmx2(bf, kbc + (uint32_t)((t0q + rB) * SD4 + k0 + cB) * 4);
                mma_tf32(a1, af, bf);
            }
            int ia = i0q + g, ib2 = ia + 8, t = t0q + 2 * q;
            float lia = Lgg[icb + ia], lib = Lgg[icb + ib2];
            float lt0 = Lgg[icb + t], lt1 = Lgg[icb + t + 1];
            float f00 = (t     <= ia)  ? __expf(lia - lt0) * CF3X : 0.f;
            float f01 = (t + 1 <= ia)  ? __expf(lia - lt1) * CF3X : 0.f;
            float f10 = (t     <= ib2) ? __expf(lib - lt0) * CF3X : 0.f;
            float f11 = (t + 1 <= ib2) ? __expf(lib - lt1) * CF3X : 0.f;
            *(float2*)(Asf + ia * SA4 + t) =
                make_float2(to_tf32(a1[0] * f00), to_tf32(a1[1] * f01));
            *(float2*)(Asf + ib2 * SA4 + t) =
                make_float2(to_tf32(a1[2] * f10), to_tf32(a1[3] * f11));
        } else {
            // odd: larger update slice
            upd_part<0, 24>(st, Vc, Kc, wv, jm0, nb0, g, q);
        }
        __syncthreads();                    // B1: As + partials visible

        if (wid & 1) {
            // odd: finish update, combine partials, A@V, store O
            upd_part<24, 32>(st, Vc, Kc, wv, jm0, nb0, g, q);
            #pragma unroll
            for (int it = 0; it < 2; it++) {
                float sa = sg[it * 16 + g], sb2 = sg[it * 16 + 8 + g];
                float acc[2][4];
                #pragma unroll
                for (int nb = 0; nb < 2; nb++) {
                    int jc = jm0 + nb * 8 + 2 * q;
                    float2 a0 = *(float2*)(R1f + (it * 16 + g) * SV4 + jc);
                    float2 b0 = *(float2*)(R0f + (it * 16 + g) * SV4 + jc);
                    float2 a1 = *(float2*)(R1f + (it * 16 + 8 + g) * SV4 + jc);
                    float2 b1 = *(float2*)(R0f + (it * 16 + 8 + g) * SV4 + jc);
                    acc[nb][0] = sa * (a0.x + b0.x);
                    acc[nb][1] = sa * (a0.y + b0.y);
                    acc[nb][2] = sb2 * (a1.x + b1.x);
                    acc[nb][3] = sb2 * (a1.y + b1.y);
                }
                #pragma unroll
                for (int k0 = 0; k0 < CI; k0 += 8) {
                    uint32_t af[4];
                    ldmx4(af, asb + (uint32_t)((it * 16 + rA) * SA4 + k0 + cA) * 4);
                    #pragma unroll
                    for (int nb = 0; nb < 2; nb++) {
                        int jc = jm0 + nb * 8 + g;
                        uint32_t bf[2] = {
                            __float_as_uint(Vc[(k0 + q) * SV4 + jc]),
                            __float_as_uint(Vc[(k0 + 4 + q) * SV4 + jc]) };
                        mma_tf32(acc[nb], af, bf);
                    }
                }
                size_t ro0 = (tok0 + icb + it * 16 + g) * DD + jh * 128;
                size_t ro1 = (tok0 + icb + it * 16 + 8 + g) * DD + jh * 128;
                #pragma unroll
                for (int nb = 0; nb < 2; nb++) {
                    int jc = jm0 + nb * 8 + 2 * q;
                    *(float2*)(O + ro0 + jc) = make_float2(acc[nb][0], acc[nb][1]);
                    *(float2*)(O + ro1 + jc) = make_float2(acc[nb][2], acc[nb][3]);
                }
            }
        } else {
            // even: finish update
            upd_part<8, 32>(st, Vc, Kc, wv, jm0, nb0, g, q);
        }
    }
}

// ---------------------------------------------------------------------------
extern "C" void kernel_launch(void* const* d_in, const int* in_sizes, int n_in,
                              void* d_out, int out_size)
{
    const float* q    = (const float*)d_in[0];
    const float* k    = (const float*)d_in[1];
    const float* v    = (const float*)d_in[2];
    const float* beta = (const float*)d_in[3];
    float* out = (float*)d_out;
    (void)in_sizes; (void)n_in; (void)out_size;

    cudaFuncSetAttribute(dr_state, cudaFuncAttributeMaxDynamicSharedMemorySize, A_SMEM);
    cudaFuncSetAttribute(dr_out,   cudaFuncAttributeMaxDynamicSharedMemorySize, C_SMEM);

    dr_state<<<dim3(NBG, 2), 512, A_SMEM>>>(k, v, beta);
    dr_scan<<<dim3(64, BB), 256>>>();
    dr_out<<<dim3(NBG, 2), 512, C_SMEM>>>(q, k, v, out);
}

// round 13
// speedup vs baseline: 1.2732x; 1.0176x over previous
#include <cuda_runtime.h>
#include <cstdint>
#include <cstddef>

#define BB 8
#define SS 4096
#define DD 256
#define GG 512      // big chunk
#define NG 8        // big chunks per batch
#define NBG 64      // total big chunks
#define CI 32       // inner chunk
#define NIC 16      // inner chunks per big chunk

// Scratch: per-big-chunk state^T [bg][j][d]; LB converts in place to the
// state ENTERING each big chunk (16.8 MB).
__device__ float g_S[(size_t)NBG * DD * DD];
__device__ float g_Lg[NBG * GG];
__device__ float g_Gamma[NBG];

// ---------------------------------------------------------------------------
// Helpers
// ---------------------------------------------------------------------------
__device__ __forceinline__ uint32_t smem_u32(const void* p) {
    uint32_t a;
    asm("{ .reg .u64 t; cvta.to.shared.u64 t, %1; cvt.u32.u64 %0, t; }"
        : "=r"(a) : "l"(p));
    return a;
}

__device__ __forceinline__ float to_tf32(float f) {
    uint32_t r;
    asm("cvt.rna.tf32.f32 %0, %1;" : "=r"(r) : "f"(f));
    return __uint_as_float(r);
}

__device__ __forceinline__ void mma_tf32(float c[4], const uint32_t a[4],
                                         const uint32_t b[2]) {
    asm volatile(
        "mma.sync.aligned.m16n8k8.row.col.f32.tf32.tf32.f32 "
        "{%0,%1,%2,%3}, {%4,%5,%6,%7}, {%8,%9}, {%0,%1,%2,%3};"
        : "+f"(c[0]), "+f"(c[1]), "+f"(c[2]), "+f"(c[3])
        : "r"(a[0]), "r"(a[1]), "r"(a[2]), "r"(a[3]), "r"(b[0]), "r"(b[1]));
}

__device__ __forceinline__ void ldmx4(uint32_t r[4], uint32_t a) {
    asm volatile("ldmatrix.sync.aligned.m8n8.x4.shared.b16 {%0,%1,%2,%3}, [%4];"
                 : "=r"(r[0]), "=r"(r[1]), "=r"(r[2]), "=r"(r[3]) : "r"(a));
}
__device__ __forceinline__ void ldmx2(uint32_t r[2], uint32_t a) {
    asm volatile("ldmatrix.sync.aligned.m8n8.x2.shared.b16 {%0,%1}, [%2];"
                 : "=r"(r[0]), "=r"(r[1]) : "r"(a));
}

__device__ __forceinline__ void cp16(uint32_t dst, const void* src) {
    asm volatile("cp.async.cg.shared.global [%0], [%1], 16;"
                 :: "r"(dst), "l"(src));
}
#define CP_COMMIT() asm volatile("cp.async.commit_group;" ::: "memory")
#define CP_WAIT0()  asm volatile("cp.async.wait_group 0;" ::: "memory")
#define CP_WAIT1()  asm volatile("cp.async.wait_group 1;" ::: "memory")
#define CP_WAIT2()  asm volatile("cp.async.wait_group 2;" ::: "memory")

// fp32 smem strides (words), ≡ 4 (mod 32): conflict-free b16-trick ldmatrix
#define SD4 260   // 256-wide rows
#define SV4 132   // 128-wide rows
#define SA4 36    // 32-wide rows

// RZ-truncation bias compensation (HMMA truncates fp32 operands to tf32).
#define CF1X 1.000338f
#define CF2X 1.000677f
#define CF3X 1.001015f

// Split state-update over k0 in [B, E). Compile-time bounds keep unrolling.
template<int B, int E>
__device__ __forceinline__ void upd_part(
    float (&st)[16][4], const float* __restrict__ Vc,
    const float* __restrict__ Kc, const float* __restrict__ wv,
    int jm0, int nb0, int g, int q)
{
    #pragma unroll
    for (int k0 = B; k0 < E; k0 += 8) {
        const int r0 = (k0 + q) * SV4, r4 = (k0 + 4 + q) * SV4;
        const int s0 = (k0 + q) * SD4, s4 = (k0 + 4 + q) * SD4;
        const float w0 = wv[k0 + q], w1 = wv[k0 + 4 + q];
        uint32_t af[4];
        af[0] = __float_as_uint(to_tf32(Vc[r0 + jm0 + g] * w0));
        af[1] = __float_as_uint(to_tf32(Vc[r0 + jm0 + 8 + g] * w0));
        af[2] = __float_as_uint(to_tf32(Vc[r4 + jm0 + g] * w1));
        af[3] = __float_as_uint(to_tf32(Vc[r4 + jm0 + 8 + g] * w1));
        #pragma unroll
        for (int nt = 0; nt < 16; nt++) {
            int d0 = nb0 + nt * 8 + g;
            uint32_t bf[2] = { __float_as_uint(Kc[s0 + d0]),
                               __float_as_uint(Kc[s4 + d0]) };
            mma_tf32(st[nt], af, bf);
        }
    }
}

// ---------------------------------------------------------------------------
// LA: quadrant re-tile. Grid (NBG, 4): qj = j-half, qi = d-half. 256 thr,
// 2 CTAs/SM, 32-token panels, 3-stage cp.async pipeline.
//   T^T[j128][d128] = sum_tau (w_tau V[tau][j]) K[tau][d]
// ---------------------------------------------------------------------------
#define A_LGG 0                          // 512 floats
#define A_WV  2048                       // 512 floats
#define A_PNL 16896                      // 32 * SV4 * 4 bytes per panel
#define A_K   4096                       // 3 panels
#define A_V   (A_K + 3 * A_PNL)          // 54784
#define A_SMEM (A_V + 3 * A_PNL)         // 105472

__device__ __forceinline__ void la_issue(
    uint32_t kbuf, uint32_t vbuf, const float* __restrict__ Kg,
    const float* __restrict__ Vg, int p, int tid)
{
    #pragma unroll
    for (int it = 0; it < 4; it++) {
        int idx = it * 256 + tid, row = idx >> 5, c4 = (idx & 31) << 2;
        cp16(kbuf + (uint32_t)(row * SV4 + c4) * 4,
             Kg + (size_t)(p * 32 + row) * DD + c4);
        cp16(vbuf + (uint32_t)(row * SV4 + c4) * 4,
             Vg + (size_t)(p * 32 + row) * DD + c4);
    }
    CP_COMMIT();
}

__global__ __launch_bounds__(256, 2) void dr_state(
    const float* __restrict__ K, const float* __restrict__ V,
    const float* __restrict__ beta)
{
    extern __shared__ char sm[];
    float* Lgg = (float*)(sm + A_LGG);
    float* wv  = (float*)(sm + A_WV);
    const uint32_t sb = smem_u32(sm);
    const int bg = blockIdx.x;
    const int qj = blockIdx.y >> 1, qi = blockIdx.y & 1;
    const int b = bg >> 3, g2 = bg & 7;
    const int tid = threadIdx.x, wid = tid >> 5, lane = tid & 31;
    const int q = lane & 3, g = lane >> 2;

    const size_t tok0 = (size_t)b * SS + (size_t)g2 * GG;
    const float* Kg = K + tok0 * DD + qi * 128;
    const float* Vg = V + tok0 * DD + qj * 128;

    // prologue: 3 panels in flight
    #pragma unroll
    for (int s = 0; s < 3; s++)
        la_issue(sb + A_K + s * A_PNL, sb + A_V + s * A_PNL, Kg, Vg, s, tid);

    // cumulative log(beta)
    Lgg[tid]       = __logf(fmaxf(beta[tok0 + tid], 1e-30f));
    Lgg[tid + 256] = __logf(fmaxf(beta[tok0 + tid + 256], 1e-30f));
    __syncthreads();
    if (wid == 0) {
        int b0 = lane * 16;
        float s = 0.f;
        #pragma unroll
        for (int u = 0; u < 16; u++) { s += Lgg[b0 + u]; Lgg[b0 + u] = s; }
        float t = s;
        #pragma unroll
        for (int d = 1; d < 32; d <<= 1) {
            float o = __shfl_up_sync(0xFFFFFFFFu, t, d);
            if (lane >= d) t += o;
        }
        float excl = t - s;
        #pragma unroll
        for (int u = 0; u < 16; u++) Lgg[b0 + u] += excl;
    }
    __syncthreads();
    const float lend = Lgg[GG - 1];
    wv[tid]       = __expf(lend - Lgg[tid]) * CF1X;
    wv[tid + 256] = __expf(lend - Lgg[tid + 256]) * CF1X;
    if (blockIdx.y == 0) {
        g_Lg[bg * GG + tid]       = Lgg[tid];
        g_Lg[bg * GG + tid + 256] = Lgg[tid + 256];
        if (tid == 0) g_Gamma[bg] = __expf(lend);
    }

    const int jm0 = (wid >> 1) * 32;   // 4 j-tiles of 32
    const int i0w = (wid & 1) * 64;    // 2 d-tiles of 64

    float acc[2][8][4];
    #pragma unroll
    for (int mt = 0; mt < 2; mt++)
        #pragma unroll
        for (int nt = 0; nt < 8; nt++)
            #pragma unroll
            for (int u = 0; u < 4; u++) acc[mt][nt][u] = 0.f;

    for (int p = 0; p < 16; p++) {
        int rem = 15 - p;                // groups issued after panel p
        if (rem >= 2)      CP_WAIT2();
        else if (rem == 1) CP_WAIT1();
        else               CP_WAIT0();
        __syncthreads();                 // panel p visible to all warps
        const int s = p % 3;
        const float* Kp = (const float*)(sm + A_K + s * A_PNL);
        const float* Vp = (const float*)(sm + A_V + s * A_PNL);
        const float* wp = wv + p * 32;

        #pragma unroll
        for (int k0 = 0; k0 < 32; k0 += 8) {
            const int r0 = (k0 + q) * SV4, r4 = (k0 + 4 + q) * SV4;
            const float w0 = wp[k0 + q], w1 = wp[k0 + 4 + q];
            uint32_t af[2][4], bf[8][2];
            #pragma unroll
            for (int mt = 0; mt < 2; mt++) {
                int jb = jm0 + mt * 16 + g;
                af[mt][0] = __float_as_uint(to_tf32(Vp[r0 + jb] * w0));
                af[mt][1] = __float_as_uint(to_tf32(Vp[r0 + jb + 8] * w0));
                af[mt][2] = __float_as_uint(to_tf32(Vp[r4 + jb] * w1));
                af[mt][3] = __float_as_uint(to_tf32(Vp[r4 + jb + 8] * w1));
            }
            #pragma unroll
            for (int nt = 0; nt < 8; nt++) {
                int db = i0w + nt * 8 + g;
                bf[nt][0] = __float_as_uint(Kp[r0 + db]);
                bf[nt][1] = __float_as_uint(Kp[r4 + db]);
            }
            #pragma unroll
            for (int mt = 0; mt < 2; mt++)
                #pragma unroll
                for (int nt = 0; nt < 8; nt++)
                    mma_tf32(acc[mt][nt], af[mt], bf[nt]);
        }
        __syncthreads();                 // all warps done with buffer s
        if (p + 3 < 16)
            la_issue(sb + A_K + s * A_PNL, sb + A_V + s * A_PNL, Kg, Vg,
                     p + 3, tid);
    }

    float* Sdst = g_S + (size_t)bg * 65536 + (size_t)(qj * 128) * 256 + qi * 128;
    #pragma unroll
    for (int mt = 0; mt < 2; mt++)
        #pragma unroll
        for (int nt = 0; nt < 8; nt++) {
            int j = jm0 + mt * 16 + g;
            int d = i0w + nt * 8 + 2 * q;
            float2 v0 = { acc[mt][nt][0], acc[mt][nt][1] };
            float2 v1 = { acc[mt][nt][2], acc[mt][nt][3] };
            *(float2*)(Sdst + (size_t)j * 256 + d) = v0;
            *(float2*)(Sdst + (size_t)(j + 8) * 256 + d) = v1;
        }
}

// ---------------------------------------------------------------------------
// LB: 8-step scan over big-chunk states (in place). (verbatim)
// ---------------------------------------------------------------------------
__global__ __launch_bounds__(256) void dr_scan()
{
    const int b = blockIdx.y;
    const size_t e4 = ((size_t)blockIdx.x * 256 + threadIdx.x) * 4;
    float4 h = { 0.f, 0.f, 0.f, 0.f };
    #pragma unroll
    for (int g2 = 0; g2 < NG; g2++) {
        const int bg = b * NG + g2;
        const size_t off = (size_t)bg * 65536 + e4;
        const float gc = g_Gamma[bg];
        float4 s = *(const float4*)(g_S + off);
        *(float4*)(g_S + off) = h;
        h.x = gc * h.x + s.x; h.y = gc * h.y + s.y;
        h.z = gc * h.z + s.z; h.w = gc * h.w + s.w;
    }
}

// ---------------------------------------------------------------------------
// LC: R12 (verified) + masked-tile skip: even warps whose QK tile is fully
// above the causal diagonal (t0q >= i0q+16) write zeros instead of MMA.
// ---------------------------------------------------------------------------
#define C_LGG 0
#define C_WVA 2048
#define C_SGA 4096
#define C_GAM 6144                      // 64 B
#define C_Q0  6272
#define C_Q1  (C_Q0 + 32 * SD4 * 4)     // 39552
#define C_K0  (C_Q1 + 32 * SD4 * 4)     // 72832
#define C_K1  (C_K0 + 32 * SD4 * 4)     // 106112
#define C_V0  (C_K1 + 32 * SD4 * 4)     // 139392
#define C_V1  (C_V0 + 32 * SV4 * 4)     // 156288
#define C_AS  (C_V1 + 32 * SV4 * 4)     // 173184
#define C_R0  (C_AS + 32 * SA4 * 4)     // 177792
#define C_R1  (C_R0 + 32 * SV4 * 4)     // 194688
#define C_SMEM (C_R1 + 32 * SV4 * 4)    // 211584

__global__ __launch_bounds__(512, 1) void dr_out(
    const float* __restrict__ Q, const float* __restrict__ K,
    const float* __restrict__ V, float* __restrict__ O)
{
    extern __shared__ char sm[];
    float* Lgg = (float*)(sm + C_LGG);
    float* wvA = (float*)(sm + C_WVA);
    float* sgA = (float*)(sm + C_SGA);
    float* gamA = (float*)(sm + C_GAM);
    float* Asf = (float*)(sm + C_AS);
    float* R0f = (float*)(sm + C_R0);
    float* R1f = (float*)(sm + C_R1);
    const uint32_t sb = smem_u32(sm);

    const int bg = blockIdx.x, jh = blockIdx.y;
    const int b = bg >> 3, g2 = bg & 7;
    const int tid = threadIdx.x, wid = tid >> 5, lane = tid & 31;
    const int q = lane & 3, g = lane >> 2;
    const int rA = lane & 15, cA = (lane >> 4) * 4;
    const int rB = lane & 7,  cB = ((lane >> 3) & 1) * 4;

    const size_t tok0 = (size_t)b * SS + (size_t)g2 * GG;
    const float* Qg = Q + tok0 * DD;
    const float* Kg = K + tok0 * DD;
    const float* Vg = V + tok0 * DD + jh * 128;

    // issue chunk 0
    {
        uint32_t qd = sb + C_Q0, kd = sb + C_K0, vd = sb + C_V0;
        #pragma unroll
        for (int it = 0; it < 4; it++) {
            int idx = it * 512 + tid, row = idx >> 6, c4 = (idx & 63) << 2;
            cp16(qd + (uint32_t)(row * SD4 + c4) * 4, Qg + (size_t)row * DD + c4);
            cp16(kd + (uint32_t)(row * SD4 + c4) * 4, Kg + (size_t)row * DD + c4);
        }
        #pragma unroll
        for (int it = 0; it < 2; it++) {
            int idx = it * 512 + tid, row = idx >> 5, c4 = (idx & 31) << 2;
            cp16(vd + (uint32_t)(row * SV4 + c4) * 4, Vg + (size_t)row * DD + c4);
        }
        CP_COMMIT();
    }

    Lgg[tid] = g_Lg[bg * GG + tid];
    __syncthreads();                        // Lgg visible

    // precompute per-chunk tables
    {
        int c = tid >> 5, p = tid & 31;
        float baseL = c ? Lgg[c * CI - 1] : 0.f;
        float lendI = Lgg[c * CI + CI - 1];
        float lt = Lgg[c * CI + p];
        wvA[tid] = __expf(lendI - lt) * CF1X;
        sgA[tid] = __expf(lt - baseL) * CF2X;
        if (tid < NIC)
            gamA[tid] = __expf(Lgg[tid * CI + CI - 1] -
                               (tid ? Lgg[tid * CI - 1] : 0.f));
    }

    // state regs: warp tile [j 16][d 128]; pairs (2w,2w+1) split d.
    const int jm0 = (wid >> 1) * 16;
    const int nb0 = (wid & 1) * 128;
    float st[16][4];
    {
        const float* Sg = g_S + (size_t)bg * 65536 + (size_t)(jh * 128) * 256;
        #pragma unroll
        for (int nt = 0; nt < 16; nt++) {
            int d = nb0 + nt * 8 + 2 * q;
            float2 lo = *(const float2*)(Sg + (size_t)(jm0 + g) * 256 + d);
            float2 hi = *(const float2*)(Sg + (size_t)(jm0 + 8 + g) * 256 + d);
            st[nt][0] = lo.x; st[nt][1] = lo.y;
            st[nt][2] = hi.x; st[nt][3] = hi.y;
        }
    }

    const int srcq = (lane & ~3) | (q >> 1);
    const uint32_t asb = sb + C_AS;

    for (int ic = 0; ic < NIC; ic++) {
        const int icb = ic * CI;
        CP_WAIT0();
        __syncthreads();                    // B0: buffers ready, prior readers done
        if (ic < NIC - 1) {
            uint32_t qd = sb + (((ic + 1) & 1) ? C_Q1 : C_Q0);
            uint32_t kd = sb + (((ic + 1) & 1) ? C_K1 : C_K0);
            uint32_t vd = sb + (((ic + 1) & 1) ? C_V1 : C_V0);
            const float* Qn = Qg + (size_t)(icb + CI) * DD;
            const float* Kn = Kg + (size_t)(icb + CI) * DD;
            const float* Vn = Vg + (size_t)(icb + CI) * DD;
            #pragma unroll
            for (int it = 0; it < 4; it++) {
                int idx = it * 512 + tid, row = idx >> 6, c4 = (idx & 63) << 2;
                cp16(qd + (uint32_t)(row * SD4 + c4) * 4, Qn + (size_t)row * DD + c4);
                cp16(kd + (uint32_t)(row * SD4 + c4) * 4, Kn + (size_t)row * DD + c4);
            }
            #pragma unroll
            for (int it = 0; it < 2; it++) {
                int idx = it * 512 + tid, row = idx >> 5, c4 = (idx & 31) << 2;
                cp16(vd + (uint32_t)(row * SV4 + c4) * 4, Vn + (size_t)row * DD + c4);
            }
            CP_COMMIT();
        }

        const float* wv = wvA + icb;
        const float* sg = sgA + icb;
        const float gamma = gamA[ic];
        const uint32_t qbc = sb + ((ic & 1) ? C_Q1 : C_Q0);
        const uint32_t kbc = sb + ((ic & 1) ? C_K1 : C_K0);
        const float* Vc = (const float*)(sm + ((ic & 1) ? C_V1 : C_V0));
        const float* Kc = (const float*)(sm + ((ic & 1) ? C_K1 : C_K0));

        // ---- Phase A (all warps): Q@H partials (pre-update state) ----
        float* Rb = (wid & 1) ? R1f : R0f;
        {
            float accP[2][2][4];
            #pragma unroll
            for (int it = 0; it < 2; it++)
                #pragma unroll
                for (int nb = 0; nb < 2; nb++)
                    #pragma unroll
                    for (int u = 0; u < 4; u++) accP[it][nb][u] = 0.f;
            #pragma unroll
            for (int nt = 0; nt < 16; nt++) {
                float s00 = __shfl_sync(0xFFFFFFFFu, st[nt][0], srcq);
                float s01 = __shfl_sync(0xFFFFFFFFu, st[nt][1], srcq);
                float s02 = __shfl_sync(0xFFFFFFFFu, st[nt][0], srcq + 2);
                float s03 = __shfl_sync(0xFFFFFFFFu, st[nt][1], srcq + 2);
                float s10 = __shfl_sync(0xFFFFFFFFu, st[nt][2], srcq);
                float s11 = __shfl_sync(0xFFFFFFFFu, st[nt][3], srcq);
                float s12 = __shfl_sync(0xFFFFFFFFu, st[nt][2], srcq + 2);
                float s13 = __shfl_sync(0xFFFFFFFFu, st[nt][3], srcq + 2);
                uint32_t blo[2] = { __float_as_uint((q & 1) ? s01 : s00),
                                    __float_as_uint((q & 1) ? s03 : s02) };
                uint32_t bhi[2] = { __float_as_uint((q & 1) ? s11 : s10),
                                    __float_as_uint((q & 1) ? s13 : s12) };
                #pragma unroll
                for (int it = 0; it < 2; it++) {
                    uint32_t af[4];
                    ldmx4(af, qbc + (uint32_t)((it * 16 + rA) * SD4 + nb0 + nt * 8 + cA) * 4);
                    mma_tf32(accP[it][0], af, blo);
                    mma_tf32(accP[it][1], af, bhi);
                }
            }
            #pragma unroll
            for (int it = 0; it < 2; it++)
                #pragma unroll
                for (int nb = 0; nb < 2; nb++) {
                    int jc = jm0 + nb * 8 + 2 * q;
                    *(float2*)(Rb + (it * 16 + g) * SV4 + jc) =
                        make_float2(accP[it][nb][0], accP[it][nb][1]);
                    *(float2*)(Rb + (it * 16 + 8 + g) * SV4 + jc) =
                        make_float2(accP[it][nb][2], accP[it][nb][3]);
                }
        }

        // gamma-scale state (both parities; update halves follow)
        #pragma unroll
        for (int nt = 0; nt < 16; nt++) {
            st[nt][0] *= gamma; st[nt][1] *= gamma;
            st[nt][2] *= gamma; st[nt][3] *= gamma;
        }

        if (!(wid & 1)) {
            // even: small update slice, then QK^T -> masked decayed A
            upd_part<0, 8>(st, Vc, Kc, wv, jm0, nb0, g, q);

            int e = wid >> 1;
            int i0q = (e >> 2) * 16, t0q = (e & 3) * 8;
            if (t0q < i0q + 16) {
                float a1[4] = { 0.f, 0.f, 0.f, 0.f };
                #pragma unroll
                for (int k0 = 0; k0 < 256; k0 += 8) {
                    uint32_t af[4], bf[2];
                    ldmx4(af, qbc + (uint32_t)((i0q + rA) * SD4 + k0 + cA) * 4);
                    ldmx2(bf, kbc + (uint32_t)((t0q + rB) * SD4 + k0 + cB) * 4);
                    mma_tf32(a1, af, bf);
                }
                int ia = i0q + g, ib2 = ia + 8, t = t0q + 2 * q;
                float lia = Lgg[icb + ia], lib = Lgg[icb + ib2];
                float lt0 = Lgg[icb + t], lt1 = Lgg[icb + t + 1];
                float f00 = (t     <= ia)  ? __expf(lia - lt0) * CF3X : 0.f;
                float f01 = (t + 1 <= ia)  ? __expf(lia - lt1) * CF3X : 0.f;
                float f10 = (t     <= ib2) ? __expf(lib - lt0) * CF3X : 0.f;
                float f11 = (t + 1 <= ib2) ? __expf(lib - lt1) * CF3X : 0.f;
                *(float2*)(Asf + ia * SA4 + t) =
                    make_float2(to_tf32(a1[0] * f00), to_tf32(a1[1] * f01));
                *(float2*)(Asf + ib2 * SA4 + t) =
                    make_float2(to_tf32(a1[2] * f10), to_tf32(a1[3] * f11));
            } else {
                // tile entirely above the causal diagonal: exact zeros
                int ia = i0q + g, ib2 = ia + 8, t = t0q + 2 * q;
                float2 z = make_float2(0.f, 0.f);
                *(float2*)(Asf + ia * SA4 + t)  = z;
                *(float2*)(Asf + ib2 * SA4 + t) = z;
            }
        } else {
            // odd: larger update slice
            upd_part<0, 24>(st, Vc, Kc, wv, jm0, nb0, g, q);
        }
        __syncthreads();                    // B1: As + partials visible

        if (wid & 1) {
            // odd: finish update, combine partials, A@V, store O
            upd_part<24, 32>(st, Vc, Kc, wv, jm0, nb0, g, q);
            #pragma unroll
            for (int it = 0; it < 2; it++) {
                float sa = sg[it * 16 + g], sb2 = sg[it * 16 + 8 + g];
                float acc[2][4];
                #pragma unroll
                for (int nb = 0; nb < 2; nb++) {
                    int jc = jm0 + nb * 8 + 2 * q;
                    float2 a0 = *(float2*)(R1f + (it * 16 + g) * SV4 + jc);
                    float2 b0 = *(float2*)(R0f + (it * 16 + g) * SV4 + jc);
                    float2 a1 = *(float2*)(R1f + (it * 16 + 8 + g) * SV4 + jc);
                    float2 b1 = *(float2*)(R0f + (it * 16 + 8 + g) * SV4 + jc);
                    acc[nb][0] = sa * (a0.x + b0.x);
                    acc[nb][1] = sa * (a0.y + b0.y);
                    acc[nb][2] = sb2 * (a1.x + b1.x);
                    acc[nb][3] = sb2 * (a1.y + b1.y);
                }
                #pragma unroll
                for (int k0 = 0; k0 < CI; k0 += 8) {
                    uint32_t af[4];
                    ldmx4(af, asb + (uint32_t)((it * 16 + rA) * SA4 + k0 + cA) * 4);
                    #pragma unroll
                    for (int nb = 0; nb < 2; nb++) {
                        int jc = jm0 + nb * 8 + g;
                        uint32_t bf[2] = {
                            __float_as_uint(Vc[(k0 + q) * SV4 + jc]),
                            __float_as_uint(Vc[(k0 + 4 + q) * SV4 + jc]) };
                        mma_tf32(acc[nb], af, bf);
                    }
                }
                size_t ro0 = (tok0 + icb + it * 16 + g) * DD + jh * 128;
                size_t ro1 = (tok0 + icb + it * 16 + 8 + g) * DD + jh * 128;
                #pragma unroll
                for (int nb = 0; nb < 2; nb++) {
                    int jc = jm0 + nb * 8 + 2 * q;
                    *(float2*)(O + ro0 + jc) = make_float2(acc[nb][0], acc[nb][1]);
                    *(float2*)(O + ro1 + jc) = make_float2(acc[nb][2], acc[nb][3]);
                }
            }
        } else {
            // even: finish update
            upd_part<8, 32>(st, Vc, Kc, wv, jm0, nb0, g, q);
        }
    }
}

// ---------------------------------------------------------------------------
extern "C" void kernel_launch(void* const* d_in, const int* in_sizes, int n_in,
                              void* d_out, int out_size)
{
    const float* q    = (const float*)d_in[0];
    const float* k    = (const float*)d_in[1];
    const float* v    = (const float*)d_in[2];
    const float* beta = (const float*)d_in[3];
    float* out = (float*)d_out;
    (void)in_sizes; (void)n_in; (void)out_size;

    cudaFuncSetAttribute(dr_state, cudaFuncAttributeMaxDynamicSharedMemorySize, A_SMEM);
    cudaFuncSetAttribute(dr_out,   cudaFuncAttributeMaxDynamicSharedMemorySize, C_SMEM);

    dr_state<<<dim3(NBG, 4), 256, A_SMEM>>>(k, v, beta);
    dr_scan<<<dim3(64, BB), 256>>>();
    dr_out<<<dim3(NBG, 2), 512, C_SMEM>>>(q, k, v, out);
}

// round 14
// speedup vs baseline: 1.3013x; 1.0221x over previous
#include <cuda_runtime.h>
#include <cstdint>
#include <cstddef>

#define BB 8
#define SS 4096
#define DD 256
#define GG 512      // big chunk
#define NG 8        // big chunks per batch
#define NBG 64      // total big chunks
#define CI 32       // inner chunk
#define NIC 16      // inner chunks per big chunk

// Scratch: per-big-chunk state^T [bg][j][d]; LB converts in place to the
// state ENTERING each big chunk (16.8 MB).
__device__ float g_S[(size_t)NBG * DD * DD];
__device__ float g_Lg[NBG * GG];
__device__ float g_Gamma[NBG];

// ---------------------------------------------------------------------------
// Helpers
// ---------------------------------------------------------------------------
__device__ __forceinline__ uint32_t smem_u32(const void* p) {
    uint32_t a;
    asm("{ .reg .u64 t; cvta.to.shared.u64 t, %1; cvt.u32.u64 %0, t; }"
        : "=r"(a) : "l"(p));
    return a;
}

__device__ __forceinline__ float to_tf32(float f) {
    uint32_t r;
    asm("cvt.rna.tf32.f32 %0, %1;" : "=r"(r) : "f"(f));
    return __uint_as_float(r);
}

__device__ __forceinline__ void mma_tf32(float c[4], const uint32_t a[4],
                                         const uint32_t b[2]) {
    asm volatile(
        "mma.sync.aligned.m16n8k8.row.col.f32.tf32.tf32.f32 "
        "{%0,%1,%2,%3}, {%4,%5,%6,%7}, {%8,%9}, {%0,%1,%2,%3};"
        : "+f"(c[0]), "+f"(c[1]), "+f"(c[2]), "+f"(c[3])
        : "r"(a[0]), "r"(a[1]), "r"(a[2]), "r"(a[3]), "r"(b[0]), "r"(b[1]));
}

__device__ __forceinline__ void ldmx4(uint32_t r[4], uint32_t a) {
    asm volatile("ldmatrix.sync.aligned.m8n8.x4.shared.b16 {%0,%1,%2,%3}, [%4];"
                 : "=r"(r[0]), "=r"(r[1]), "=r"(r[2]), "=r"(r[3]) : "r"(a));
}
__device__ __forceinline__ void ldmx2(uint32_t r[2], uint32_t a) {
    asm volatile("ldmatrix.sync.aligned.m8n8.x2.shared.b16 {%0,%1}, [%2];"
                 : "=r"(r[0]), "=r"(r[1]) : "r"(a));
}

__device__ __forceinline__ void cp16(uint32_t dst, const void* src) {
    asm volatile("cp.async.cg.shared.global [%0], [%1], 16;"
                 :: "r"(dst), "l"(src));
}
#define CP_COMMIT() asm volatile("cp.async.commit_group;" ::: "memory")
#define CP_WAIT0()  asm volatile("cp.async.wait_group 0;" ::: "memory")

#define BAR_ARRIVE(id, cnt) \
    asm volatile("bar.arrive %0, %1;" :: "r"(id), "r"(cnt) : "memory")
#define BAR_SYNC(id, cnt) \
    asm volatile("bar.sync %0, %1;" :: "r"(id), "r"(cnt) : "memory")

// fp32 smem strides (words), ≡ 4 (mod 32): conflict-free b16-trick ldmatrix
#define SD4 260   // 256-wide rows
#define SV4 132   // 128-wide rows
#define SA4 36    // 32-wide rows

// RZ-truncation bias compensation (HMMA truncates fp32 operands to tf32).
#define CF1X 1.000338f
#define CF2X 1.000677f
#define CF3X 1.001015f

// Split state-update over k0 in [B, E). Compile-time bounds keep unrolling.
template<int B, int E>
__device__ __forceinline__ void upd_part(
    float (&st)[16][4], const float* __restrict__ Vc,
    const float* __restrict__ Kc, const float* __restrict__ wv,
    int jm0, int nb0, int g, int q)
{
    #pragma unroll
    for (int k0 = B; k0 < E; k0 += 8) {
        const int r0 = (k0 + q) * SV4, r4 = (k0 + 4 + q) * SV4;
        const int s0 = (k0 + q) * SD4, s4 = (k0 + 4 + q) * SD4;
        const float w0 = wv[k0 + q], w1 = wv[k0 + 4 + q];
        uint32_t af[4];
        af[0] = __float_as_uint(to_tf32(Vc[r0 + jm0 + g] * w0));
        af[1] = __float_as_uint(to_tf32(Vc[r0 + jm0 + 8 + g] * w0));
        af[2] = __float_as_uint(to_tf32(Vc[r4 + jm0 + g] * w1));
        af[3] = __float_as_uint(to_tf32(Vc[r4 + jm0 + 8 + g] * w1));
        #pragma unroll
        for (int nt = 0; nt < 16; nt++) {
            int d0 = nb0 + nt * 8 + g;
            uint32_t bf[2] = { __float_as_uint(Kc[s0 + d0]),
                               __float_as_uint(Kc[s4 + d0]) };
            mma_tf32(st[nt], af, bf);
        }
    }
}

// ---------------------------------------------------------------------------
// LA: big-chunk state contribution T^T[j][d] per (bg, j-half). 512 threads.
// (R12-verbatim — verified 43.4us)
// ---------------------------------------------------------------------------
#define A_LGG 0
#define A_WV  2048
#define A_K0  4096
#define A_K1  (A_K0 + 64 * SD4 * 4)
#define A_V0  (A_K1 + 64 * SD4 * 4)
#define A_V1  (A_V0 + 64 * SV4 * 4)
#define A_SMEM (A_V1 + 64 * SV4 * 4)   // 204800

__global__ __launch_bounds__(512, 1) void dr_state(
    const float* __restrict__ K, const float* __restrict__ V,
    const float* __restrict__ beta)
{
    extern __shared__ char sm[];
    float* Lgg = (float*)(sm + A_LGG);
    float* wv  = (float*)(sm + A_WV);
    const uint32_t sb = smem_u32(sm);
    const int bg = blockIdx.x, qj = blockIdx.y;
    const int b = bg >> 3, g2 = bg & 7;
    const int tid = threadIdx.x, wid = tid >> 5, lane = tid & 31;
    const int q = lane & 3, g = lane >> 2;

    const size_t tok0 = (size_t)b * SS + (size_t)g2 * GG;
    const float* Kg = K + tok0 * DD;
    const float* Vg = V + tok0 * DD + qj * 128;

    {
        uint32_t kd = sb + A_K0, vd = sb + A_V0;
        #pragma unroll
        for (int it = 0; it < 8; it++) {
            int idx = it * 512 + tid, row = idx >> 6, c4 = (idx & 63) << 2;
            cp16(kd + (uint32_t)(row * SD4 + c4) * 4, Kg + (size_t)row * DD + c4);
        }
        #pragma unroll
        for (int it = 0; it < 4; it++) {
            int idx = it * 512 + tid, row = idx >> 5, c4 = (idx & 31) << 2;
            cp16(vd + (uint32_t)(row * SV4 + c4) * 4, Vg + (size_t)row * DD + c4);
        }
        CP_COMMIT();
    }

    Lgg[tid] = __logf(fmaxf(beta[tok0 + tid], 1e-30f));
    __syncthreads();
    if (wid == 0) {
        int b0 = lane * 16;
        float s = 0.f;
        #pragma unroll
        for (int u = 0; u < 16; u++) { s += Lgg[b0 + u]; Lgg[b0 + u] = s; }
        float t = s;
        #pragma unroll
        for (int d = 1; d < 32; d <<= 1) {
            float o = __shfl_up_sync(0xFFFFFFFFu, t, d);
            if (lane >= d) t += o;
        }
        float excl = t - s;
        #pragma unroll
        for (int u = 0; u < 16; u++) Lgg[b0 + u] += excl;
    }
    __syncthreads();
    const float lend = Lgg[GG - 1];
    wv[tid] = __expf(lend - Lgg[tid]) * CF1X;
    if (qj == 0) {
        g_Lg[bg * GG + tid] = Lgg[tid];
        if (tid == 0) g_Gamma[bg] = __expf(lend);
    }

    const int jm0 = (wid >> 2) * 32;
    const int i0w = (wid & 3) * 64;

    float acc[2][8][4];
    #pragma unroll
    for (int mt = 0; mt < 2; mt++)
        #pragma unroll
        for (int nt = 0; nt < 8; nt++)
            #pragma unroll
            for (int u = 0; u < 4; u++) acc[mt][nt][u] = 0.f;

    for (int p = 0; p < 8; p++) {
        CP_WAIT0();
        __syncthreads();
        if (p < 7) {
            uint32_t kd = sb + (((p + 1) & 1) ? A_K1 : A_K0);
            uint32_t vd = sb + (((p + 1) & 1) ? A_V1 : A_V0);
            const float* Kn = Kg + (size_t)(p + 1) * 64 * DD;
            const float* Vn = Vg + (size_t)(p + 1) * 64 * DD;
            #pragma unroll
            for (int it = 0; it < 8; it++) {
                int idx = it * 512 + tid, row = idx >> 6, c4 = (idx & 63) << 2;
                cp16(kd + (uint32_t)(row * SD4 + c4) * 4, Kn + (size_t)row * DD + c4);
            }
            #pragma unroll
            for (int it = 0; it < 4; it++) {
                int idx = it * 512 + tid, row = idx >> 5, c4 = (idx & 31) << 2;
                cp16(vd + (uint32_t)(row * SV4 + c4) * 4, Vn + (size_t)row * DD + c4);
            }
            CP_COMMIT();
        }
        const float* Kp = (const float*)(sm + ((p & 1) ? A_K1 : A_K0));
        const float* Vp = (const float*)(sm + ((p & 1) ? A_V1 : A_V0));
        const float* wp = wv + p * 64;

        #pragma unroll
        for (int k0 = 0; k0 < 64; k0 += 8) {
            const int r0 = (k0 + q) * SV4, r4 = (k0 + 4 + q) * SV4;
            const int s0 = (k0 + q) * SD4, s4 = (k0 + 4 + q) * SD4;
            const float w0 = wp[k0 + q], w1 = wp[k0 + 4 + q];
            uint32_t af[2][4], bf[8][2];
            #pragma unroll
            for (int mt = 0; mt < 2; mt++) {
                int jb = jm0 + mt * 16 + g;
                af[mt][0] = __float_as_uint(to_tf32(Vp[r0 + jb] * w0));
                af[mt][1] = __float_as_uint(to_tf32(Vp[r0 + jb + 8] * w0));
                af[mt][2] = __float_as_uint(to_tf32(Vp[r4 + jb] * w1));
                af[mt][3] = __float_as_uint(to_tf32(Vp[r4 + jb + 8] * w1));
            }
            #pragma unroll
            for (int nt = 0; nt < 8; nt++) {
                int db = i0w + nt * 8 + g;
                bf[nt][0] = __float_as_uint(Kp[s0 + db]);
                bf[nt][1] = __float_as_uint(Kp[s4 + db]);
            }
            #pragma unroll
            for (int mt = 0; mt < 2; mt++)
                #pragma unroll
                for (int nt = 0; nt < 8; nt++)
                    mma_tf32(acc[mt][nt], af[mt], bf[nt]);
        }
    }

    float* Sdst = g_S + (size_t)bg * 65536 + (size_t)(qj * 128) * 256;
    #pragma unroll
    for (int mt = 0; mt < 2; mt++)
        #pragma unroll
        for (int nt = 0; nt < 8; nt++) {
            int j = jm0 + mt * 16 + g;
            int d = i0w + nt * 8 + 2 * q;
            float2 v0 = { acc[mt][nt][0], acc[mt][nt][1] };
            float2 v1 = { acc[mt][nt][2], acc[mt][nt][3] };
            *(float2*)(Sdst + (size_t)j * 256 + d) = v0;
            *(float2*)(Sdst + (size_t)(j + 8) * 256 + d) = v1;
        }
}

// ---------------------------------------------------------------------------
// LB: 8-step scan over big-chunk states (in place). (verbatim)
// ---------------------------------------------------------------------------
__global__ __launch_bounds__(256) void dr_scan()
{
    const int b = blockIdx.y;
    const size_t e4 = ((size_t)blockIdx.x * 256 + threadIdx.x) * 4;
    float4 h = { 0.f, 0.f, 0.f, 0.f };
    #pragma unroll
    for (int g2 = 0; g2 < NG; g2++) {
        const int bg = b * NG + g2;
        const size_t off = (size_t)bg * 65536 + e4;
        const float gc = g_Gamma[bg];
        float4 s = *(const float4*)(g_S + off);
        *(float4*)(g_S + off) = h;
        h.x = gc * h.x + s.x; h.y = gc * h.y + s.y;
        h.z = gc * h.z + s.z; h.w = gc * h.w + s.w;
    }
}

// ---------------------------------------------------------------------------
// LC: R13 + B1 as producer/consumer named barrier (even arrive, odd sync) +
// constant-zero As tiles hoisted out of the chunk loop.
// ---------------------------------------------------------------------------
#define C_LGG 0
#define C_WVA 2048
#define C_SGA 4096
#define C_GAM 6144                      // 64 B
#define C_Q0  6272
#define C_Q1  (C_Q0 + 32 * SD4 * 4)     // 39552
#define C_K0  (C_Q1 + 32 * SD4 * 4)     // 72832
#define C_K1  (C_K0 + 32 * SD4 * 4)     // 106112
#define C_V0  (C_K1 + 32 * SD4 * 4)     // 139392
#define C_V1  (C_V0 + 32 * SV4 * 4)     // 156288
#define C_AS  (C_V1 + 32 * SV4 * 4)     // 173184
#define C_R0  (C_AS + 32 * SA4 * 4)     // 177792
#define C_R1  (C_R0 + 32 * SV4 * 4)     // 194688
#define C_SMEM (C_R1 + 32 * SV4 * 4)    // 211584

__global__ __launch_bounds__(512, 1) void dr_out(
    const float* __restrict__ Q, const float* __restrict__ K,
    const float* __restrict__ V, float* __restrict__ O)
{
    extern __shared__ char sm[];
    float* Lgg = (float*)(sm + C_LGG);
    float* wvA = (float*)(sm + C_WVA);
    float* sgA = (float*)(sm + C_SGA);
    float* gamA = (float*)(sm + C_GAM);
    float* Asf = (float*)(sm + C_AS);
    float* R0f = (float*)(sm + C_R0);
    float* R1f = (float*)(sm + C_R1);
    const uint32_t sb = smem_u32(sm);

    const int bg = blockIdx.x, jh = blockIdx.y;
    const int b = bg >> 3, g2 = bg & 7;
    const int tid = threadIdx.x, wid = tid >> 5, lane = tid & 31;
    const int q = lane & 3, g = lane >> 2;
    const int rA = lane & 15, cA = (lane >> 4) * 4;
    const int rB = lane & 7,  cB = ((lane >> 3) & 1) * 4;

    const size_t tok0 = (size_t)b * SS + (size_t)g2 * GG;
    const float* Qg = Q + tok0 * DD;
    const float* Kg = K + tok0 * DD;
    const float* Vg = V + tok0 * DD + jh * 128;

    // issue chunk 0
    {
        uint32_t qd = sb + C_Q0, kd = sb + C_K0, vd = sb + C_V0;
        #pragma unroll
        for (int it = 0; it < 4; it++) {
            int idx = it * 512 + tid, row = idx >> 6, c4 = (idx & 63) << 2;
            cp16(qd + (uint32_t)(row * SD4 + c4) * 4, Qg + (size_t)row * DD + c4);
            cp16(kd + (uint32_t)(row * SD4 + c4) * 4, Kg + (size_t)row * DD + c4);
        }
        #pragma unroll
        for (int it = 0; it < 2; it++) {
            int idx = it * 512 + tid, row = idx >> 5, c4 = (idx & 31) << 2;
            cp16(vd + (uint32_t)(row * SV4 + c4) * 4, Vg + (size_t)row * DD + c4);
        }
        CP_COMMIT();
    }

    Lgg[tid] = g_Lg[bg * GG + tid];

    // constant-zero As tiles (fully above the causal diagonal): write ONCE.
    // Rows 0..15, cols 16..31 are never produced by any computing warp.
    if (tid < 128) {
        int r = tid >> 3, c = (tid & 7) * 2 + 16;
        *(float2*)(Asf + r * SA4 + c) = make_float2(0.f, 0.f);
    }
    __syncthreads();                        // Lgg + As zeros visible

    // precompute per-chunk tables
    {
        int c = tid >> 5, p = tid & 31;
        float baseL = c ? Lgg[c * CI - 1] : 0.f;
        float lendI = Lgg[c * CI + CI - 1];
        float lt = Lgg[c * CI + p];
        wvA[tid] = __expf(lendI - lt) * CF1X;
        sgA[tid] = __expf(lt - baseL) * CF2X;
        if (tid < NIC)
            gamA[tid] = __expf(Lgg[tid * CI + CI - 1] -
                               (tid ? Lgg[tid * CI - 1] : 0.f));
    }

    // state regs: warp tile [j 16][d 128]; pairs (2w,2w+1) split d.
    const int jm0 = (wid >> 1) * 16;
    const int nb0 = (wid & 1) * 128;
    float st[16][4];
    {
        const float* Sg = g_S + (size_t)bg * 65536 + (size_t)(jh * 128) * 256;
        #pragma unroll
        for (int nt = 0; nt < 16; nt++) {
            int d = nb0 + nt * 8 + 2 * q;
            float2 lo = *(const float2*)(Sg + (size_t)(jm0 + g) * 256 + d);
            float2 hi = *(const float2*)(Sg + (size_t)(jm0 + 8 + g) * 256 + d);
            st[nt][0] = lo.x; st[nt][1] = lo.y;
            st[nt][2] = hi.x; st[nt][3] = hi.y;
        }
    }

    const int srcq = (lane & ~3) | (q >> 1);
    const uint32_t asb = sb + C_AS;

    for (int ic = 0; ic < NIC; ic++) {
        const int icb = ic * CI;
        CP_WAIT0();
        __syncthreads();                    // B0: buffers ready, prior readers done
        if (ic < NIC - 1) {
            uint32_t qd = sb + (((ic + 1) & 1) ? C_Q1 : C_Q0);
            uint32_t kd = sb + (((ic + 1) & 1) ? C_K1 : C_K0);
            uint32_t vd = sb + (((ic + 1) & 1) ? C_V1 : C_V0);
            const float* Qn = Qg + (size_t)(icb + CI) * DD;
            const float* Kn = Kg + (size_t)(icb + CI) * DD;
            const float* Vn = Vg + (size_t)(icb + CI) * DD;
            #pragma unroll
            for (int it = 0; it < 4; it++) {
                int idx = it * 512 + tid, row = idx >> 6, c4 = (idx & 63) << 2;
                cp16(qd + (uint32_t)(row * SD4 + c4) * 4, Qn + (size_t)row * DD + c4);
                cp16(kd + (uint32_t)(row * SD4 + c4) * 4, Kn + (size_t)row * DD + c4);
            }
            #pragma unroll
            for (int it = 0; it < 2; it++) {
                int idx = it * 512 + tid, row = idx >> 5, c4 = (idx & 31) << 2;
                cp16(vd + (uint32_t)(row * SV4 + c4) * 4, Vn + (size_t)row * DD + c4);
            }
            CP_COMMIT();
        }

        const float* wv = wvA + icb;
        const float* sg = sgA + icb;
        const float gamma = gamA[ic];
        const uint32_t qbc = sb + ((ic & 1) ? C_Q1 : C_Q0);
        const uint32_t kbc = sb + ((ic & 1) ? C_K1 : C_K0);
        const float* Vc = (const float*)(sm + ((ic & 1) ? C_V1 : C_V0));
        const float* Kc = (const float*)(sm + ((ic & 1) ? C_K1 : C_K0));

        // ---- Phase A (all warps): Q@H partials (pre-update state) ----
        float* Rb = (wid & 1) ? R1f : R0f;
        {
            float accP[2][2][4];
            #pragma unroll
            for (int it = 0; it < 2; it++)
                #pragma unroll
                for (int nb = 0; nb < 2; nb++)
                    #pragma unroll
                    for (int u = 0; u < 4; u++) accP[it][nb][u] = 0.f;
            #pragma unroll
            for (int nt = 0; nt < 16; nt++) {
                float s00 = __shfl_sync(0xFFFFFFFFu, st[nt][0], srcq);
                float s01 = __shfl_sync(0xFFFFFFFFu, st[nt][1], srcq);
                float s02 = __shfl_sync(0xFFFFFFFFu, st[nt][0], srcq + 2);
                float s03 = __shfl_sync(0xFFFFFFFFu, st[nt][1], srcq + 2);
                float s10 = __shfl_sync(0xFFFFFFFFu, st[nt][2], srcq);
                float s11 = __shfl_sync(0xFFFFFFFFu, st[nt][3], srcq);
                float s12 = __shfl_sync(0xFFFFFFFFu, st[nt][2], srcq + 2);
                float s13 = __shfl_sync(0xFFFFFFFFu, st[nt][3], srcq + 2);
                uint32_t blo[2] = { __float_as_uint((q & 1) ? s01 : s00),
                                    __float_as_uint((q & 1) ? s03 : s02) };
                uint32_t bhi[2] = { __float_as_uint((q & 1) ? s11 : s10),
                                    __float_as_uint((q & 1) ? s13 : s12) };
                #pragma unroll
                for (int it = 0; it < 2; it++) {
                    uint32_t af[4];
                    ldmx4(af, qbc + (uint32_t)((it * 16 + rA) * SD4 + nb0 + nt * 8 + cA) * 4);
                    mma_tf32(accP[it][0], af, blo);
                    mma_tf32(accP[it][1], af, bhi);
                }
            }
            #pragma unroll
            for (int it = 0; it < 2; it++)
                #pragma unroll
                for (int nb = 0; nb < 2; nb++) {
                    int jc = jm0 + nb * 8 + 2 * q;
                    *(float2*)(Rb + (it * 16 + g) * SV4 + jc) =
                        make_float2(accP[it][nb][0], accP[it][nb][1]);
                    *(float2*)(Rb + (it * 16 + 8 + g) * SV4 + jc) =
                        make_float2(accP[it][nb][2], accP[it][nb][3]);
                }
        }

        // gamma-scale state (both parities; update halves follow)
        #pragma unroll
        for (int nt = 0; nt < 16; nt++) {
            st[nt][0] *= gamma; st[nt][1] *= gamma;
            st[nt][2] *= gamma; st[nt][3] *= gamma;
        }

        if (!(wid & 1)) {
            // even: small update slice, then QK^T -> masked decayed A
            upd_part<0, 8>(st, Vc, Kc, wv, jm0, nb0, g, q);

            int e = wid >> 1;
            int i0q = (e >> 2) * 16, t0q = (e & 3) * 8;
            if (t0q < i0q + 16) {
                float a1[4] = { 0.f, 0.f, 0.f, 0.f };
                #pragma unroll
                for (int k0 = 0; k0 < 256; k0 += 8) {
                    uint32_t af[4], bf[2];
                    ldmx4(af, qbc + (uint32_t)((i0q + rA) * SD4 + k0 + cA) * 4);
                    ldmx2(bf, kbc + (uint32_t)((t0q + rB) * SD4 + k0 + cB) * 4);
                    mma_tf32(a1, af, bf);
                }
                int ia = i0q + g, ib2 = ia + 8, t = t0q + 2 * q;
                float lia = Lgg[icb + ia], lib = Lgg[icb + ib2];
                float lt0 = Lgg[icb + t], lt1 = Lgg[icb + t + 1];
                float f00 = (t     <= ia)  ? __expf(lia - lt0) * CF3X : 0.f;
                float f01 = (t + 1 <= ia)  ? __expf(lia - lt1) * CF3X : 0.f;
                float f10 = (t     <= ib2) ? __expf(lib - lt0) * CF3X : 0.f;
                float f11 = (t + 1 <= ib2) ? __expf(lib - lt1) * CF3X : 0.f;
                *(float2*)(Asf + ia * SA4 + t) =
                    make_float2(to_tf32(a1[0] * f00), to_tf32(a1[1] * f01));
                *(float2*)(Asf + ib2 * SA4 + t) =
                    make_float2(to_tf32(a1[2] * f10), to_tf32(a1[3] * f11));
            }
            // B1 producer side: even's Phase-B work has no cross-warp deps.
            BAR_ARRIVE(1, 512);
            // even: finish update (overlaps odd's combine/AV/stores)
            upd_part<8, 32>(st, Vc, Kc, wv, jm0, nb0, g, q);
        } else {
            // odd: larger update slice
            upd_part<0, 24>(st, Vc, Kc, wv, jm0, nb0, g, q);
            // B1 consumer side: wait for even's As + R0f partials.
            BAR_SYNC(1, 512);
            // odd: finish update, combine partials, A@V, store O
            upd_part<24, 32>(st, Vc, Kc, wv, jm0, nb0, g, q);
            #pragma unroll
            for (int it = 0; it < 2; it++) {
                float sa = sg[it * 16 + g], sb2 = sg[it * 16 + 8 + g];
                float acc[2][4];
                #pragma unroll
                for (int nb = 0; nb < 2; nb++) {
                    int jc = jm0 + nb * 8 + 2 * q;
                    float2 a0 = *(float2*)(R1f + (it * 16 + g) * SV4 + jc);
                    float2 b0 = *(float2*)(R0f + (it * 16 + g) * SV4 + jc);
                    float2 a1 = *(float2*)(R1f + (it * 16 + 8 + g) * SV4 + jc);
                    float2 b1 = *(float2*)(R0f + (it * 16 + 8 + g) * SV4 + jc);
                    acc[nb][0] = sa * (a0.x + b0.x);
                    acc[nb][1] = sa * (a0.y + b0.y);
                    acc[nb][2] = sb2 * (a1.x + b1.x);
                    acc[nb][3] = sb2 * (a1.y + b1.y);
                }
                #pragma unroll
                for (int k0 = 0; k0 < CI; k0 += 8) {
                    uint32_t af[4];
                    ldmx4(af, asb + (uint32_t)((it * 16 + rA) * SA4 + k0 + cA) * 4);
                    #pragma unroll
                    for (int nb = 0; nb < 2; nb++) {
                        int jc = jm0 + nb * 8 + g;
                        uint32_t bf[2] = {
                            __float_as_uint(Vc[(k0 + q) * SV4 + jc]),
                            __float_as_uint(Vc[(k0 + 4 + q) * SV4 + jc]) };
                        mma_tf32(acc[nb], af, bf);
                    }
                }
                size_t ro0 = (tok0 + icb + it * 16 + g) * DD + jh * 128;
                size_t ro1 = (tok0 + icb + it * 16 + 8 + g) * DD + jh * 128;
                #pragma unroll
                for (int nb = 0; nb < 2; nb++) {
                    int jc = jm0 + nb * 8 + 2 * q;
                    *(float2*)(O + ro0 + jc) = make_float2(acc[nb][0], acc[nb][1]);
                    *(float2*)(O + ro1 + jc) = make_float2(acc[nb][2], acc[nb][3]);
                }
            }
        }
    }
}

// ---------------------------------------------------------------------------
extern "C" void kernel_launch(void* const* d_in, const int* in_sizes, int n_in,
                              void* d_out, int out_size)
{
    const float* q    = (const float*)d_in[0];
    const float* k    = (const float*)d_in[1];
    const float* v    = (const float*)d_in[2];
    const float* beta = (const float*)d_in[3];
    float* out = (float*)d_out;
    (void)in_sizes; (void)n_in; (void)out_size;

    cudaFuncSetAttribute(dr_state, cudaFuncAttributeMaxDynamicSharedMemorySize, A_SMEM);
    cudaFuncSetAttribute(dr_out,   cudaFuncAttributeMaxDynamicSharedMemorySize, C_SMEM);

    dr_state<<<dim3(NBG, 2), 512, A_SMEM>>>(k, v, beta);
    dr_scan<<<dim3(64, BB), 256>>>();
    dr_out<<<dim3(NBG, 2), 512, C_SMEM>>>(q, k, v, out);
}